// round 1
// baseline (speedup 1.0000x reference)
#include <cuda_runtime.h>

#define Nn 16
#define Cc 64
#define Hh 128
#define Ww 128
#define WP 132   // width padded by 2 on each side

// shared layout (floats):
//   xs [3][Cc][WP]      rows h-1,h,h+1, zero-padded        = 25344
//   w3s[Cc][5][Cc]      (ci,k,co) transposed for broadcast = 20480
//   w7s[Cc][9]                                             =   576
// total = 46400 floats = 185600 bytes -> 1 CTA/SM
#define XS_FLOATS   (3 * Cc * WP)
#define W3S_FLOATS  (Cc * 5 * Cc)
#define W7S_FLOATS  (Cc * 9)
#define SMEM_FLOATS (XS_FLOATS + W3S_FLOATS + W7S_FLOATS)
#define SMEM_BYTES  (SMEM_FLOATS * 4)

__global__ __launch_bounds__(256, 1)
void fused_unfold_conv_kernel(const float* __restrict__ x,
                              const float* __restrict__ w3,
                              const float* __restrict__ w7,
                              float* __restrict__ out)
{
    extern __shared__ float sh[];
    float* xs  = sh;                        // [3][Cc][WP]
    float* w3s = sh + XS_FLOATS;            // [ci][k][co]
    float* w7s = w3s + W3S_FLOATS;          // [c][9]

    const int tid = threadIdx.x;
    const int h   = blockIdx.x % Hh;
    const int n   = blockIdx.x / Hh;

    // ---- stage x rows h-1, h, h+1 (zero-padded width + height) ----
    const float* xn = x + (size_t)n * Cc * Hh * Ww;
    for (int idx = tid; idx < XS_FLOATS; idx += 256) {
        int r   = idx / (Cc * WP);          // 0..2 -> row h-1+r
        int rem = idx - r * (Cc * WP);
        int c   = rem / WP;
        int p   = rem - c * WP;             // padded width index
        int hh  = h + r - 1;
        int ww  = p - 2;
        float v = 0.f;
        if (hh >= 0 && hh < Hh && ww >= 0 && ww < Ww)
            v = xn[((size_t)c * Hh + hh) * Ww + ww];
        xs[idx] = v;
    }
    // ---- stage w3 transposed: w3s[ci][k][co] = w3[co][ci][0][k] ----
    for (int idx = tid; idx < W3S_FLOATS; idx += 256) {
        int co = idx & (Cc - 1);
        int k  = (idx / Cc) % 5;
        int ci = idx / (Cc * 5);
        w3s[idx] = w3[((size_t)co * Cc + ci) * 5 + k];
    }
    for (int idx = tid; idx < W7S_FLOATS; idx += 256)
        w7s[idx] = w7[idx];
    __syncthreads();

    // thread tile: 8 output channels x 4 width positions
    const int tw  = tid & 31;               // w group
    const int tc  = tid >> 5;               // co group
    const int w0  = tw * 4;
    const int co0 = tc * 8;

    float acc[8][4];
    #pragma unroll
    for (int a = 0; a < 8; a++)
        #pragma unroll
        for (int b = 0; b < 4; b++) acc[a][b] = 0.f;

    // ---- t3: 1x5 conv with channel mixing (the GEMM-like hot loop) ----
    const float* xrow = xs + Cc * WP;       // row h (plane 1)
    for (int ci = 0; ci < Cc; ci++) {
        // x[w0-2 .. w0+5] at padded indices w0 .. w0+7 (16B-aligned)
        const float4* xp4 = reinterpret_cast<const float4*>(xrow + ci * WP + w0);
        float4 x0 = xp4[0];
        float4 x1 = xp4[1];
        float xv[8] = {x0.x, x0.y, x0.z, x0.w, x1.x, x1.y, x1.z, x1.w};

        const float* wp = w3s + (ci * 5) * Cc + co0;
        #pragma unroll
        for (int k = 0; k < 5; k++) {
            const float4* wp4 = reinterpret_cast<const float4*>(wp + k * Cc);
            float4 wa = wp4[0];
            float4 wb = wp4[1];
            float wv[8] = {wa.x, wa.y, wa.z, wa.w, wb.x, wb.y, wb.z, wb.w};
            #pragma unroll
            for (int a = 0; a < 8; a++)
                #pragma unroll
                for (int b = 0; b < 4; b++)
                    acc[a][b] = fmaf(wv[a], xv[b + k], acc[a][b]);
        }
    }

    // ---- epilogue: t1 / t5(roll=1) / max / grouped 1x1 (t7), times t3 ----
    const size_t obase = ((size_t)n * Cc) * Hh * Ww + (size_t)h * Ww;
    #pragma unroll
    for (int a = 0; a < 8; a++) {
        const int c = co0 + a;
        const float* w7c = w7s + c * 9;
        float wk[9];
        #pragma unroll
        for (int q = 0; q < 9; q++) wk[q] = w7c[q];

        const float* rh = xs + (Cc + c) * WP;        // row h, channel c
        #pragma unroll
        for (int b = 0; b < 4; b++) {
            const int w  = w0 + b;
            const int wr = (w == 0) ? (Ww - 1) : (w - 1);   // roll by SHIFT=1

            // t1[c,i,h,w] = x[c,h,w+2i-2] -> padded idx w+2i
            float t1v[3];
            #pragma unroll
            for (int i = 0; i < 3; i++) t1v[i] = rh[w + 2 * i];

            float t7 = 0.f;
            #pragma unroll
            for (int i = 0; i < 3; i++) {            // height offset (row i)
                const float* ri = xs + ((size_t)i * Cc + c) * WP;
                #pragma unroll
                for (int j = 0; j < 3; j++) {        // t5 width offset
                    // t5 = x[c, h+i-1, wr+2j-2] -> plane i, padded idx wr+2j
                    float t5v = ri[wr + 2 * j];
                    float m = fmaxf(t1v[i], t5v);
                    t7 = fmaf(wk[3 * j + i], m, t7);
                }
            }
            out[obase + (size_t)c * Hh * Ww + w] = t7 * acc[a][b];
        }
    }
}

extern "C" void kernel_launch(void* const* d_in, const int* in_sizes, int n_in,
                              void* d_out, int out_size)
{
    const float* x  = (const float*)d_in[0];
    const float* w3 = (const float*)d_in[1];
    const float* w7 = (const float*)d_in[2];
    float* out = (float*)d_out;

    cudaFuncSetAttribute(fused_unfold_conv_kernel,
                         cudaFuncAttributeMaxDynamicSharedMemorySize, SMEM_BYTES);
    fused_unfold_conv_kernel<<<Nn * Hh, 256, SMEM_BYTES>>>(x, w3, w7, out);
}

// round 2
// speedup vs baseline: 1.2223x; 1.2223x over previous
#include <cuda_runtime.h>

#define Nn 16
#define Cc 64
#define Hh 128
#define Ww 128
#define WP 132   // width padded by 2 on each side

// shared layout (floats):
//   xs [3][Cc][WP]      rows h-1,h,h+1, zero-padded        = 25344
//   w3s[Cc][5][Cc]      (ci,k,co) transposed for broadcast = 20480
//   w7s[Cc][9]                                             =   576
#define XS_FLOATS   (3 * Cc * WP)
#define W3S_FLOATS  (Cc * 5 * Cc)
#define W7S_FLOATS  (Cc * 9)
#define SMEM_FLOATS (XS_FLOATS + W3S_FLOATS + W7S_FLOATS)
#define SMEM_BYTES  (SMEM_FLOATS * 4)

#define NTHREADS 512

// ---- packed f32x2 helpers (FFMA2 path; ptxas never auto-fuses this) ----
__device__ __forceinline__ unsigned long long pack2(float lo, float hi) {
    unsigned long long r;
    asm("mov.b64 %0, {%1,%2};" : "=l"(r) : "f"(lo), "f"(hi));
    return r;
}
__device__ __forceinline__ void fma2(unsigned long long& d,
                                     unsigned long long a,
                                     unsigned long long b) {
    asm("fma.rn.f32x2 %0, %1, %2, %0;" : "+l"(d) : "l"(a), "l"(b));
}
__device__ __forceinline__ void unpack2(unsigned long long v, float& lo, float& hi) {
    asm("mov.b64 {%0,%1}, %2;" : "=f"(lo), "=f"(hi) : "l"(v));
}

__global__ __launch_bounds__(NTHREADS, 1)
void fused_unfold_conv_kernel(const float* __restrict__ x,
                              const float* __restrict__ w3,
                              const float* __restrict__ w7,
                              float* __restrict__ out)
{
    extern __shared__ float sh[];
    float* xs  = sh;                        // [3][Cc][WP]
    float* w3s = sh + XS_FLOATS;            // [ci][k][co]
    float* w7s = w3s + W3S_FLOATS;          // [c][9]

    const int tid = threadIdx.x;
    const int h   = blockIdx.x % Hh;
    const int n   = blockIdx.x / Hh;

    // ---- stage x rows h-1, h, h+1 (zero-padded width + height) ----
    const float* xn = x + (size_t)n * Cc * Hh * Ww;
    for (int idx = tid; idx < XS_FLOATS; idx += NTHREADS) {
        int r   = idx / (Cc * WP);          // 0..2 -> row h-1+r
        int rem = idx - r * (Cc * WP);
        int c   = rem / WP;
        int p   = rem - c * WP;             // padded width index
        int hh  = h + r - 1;
        int ww  = p - 2;
        float v = 0.f;
        if (hh >= 0 && hh < Hh && (unsigned)ww < (unsigned)Ww)
            v = xn[((size_t)c * Hh + hh) * Ww + ww];
        xs[idx] = v;
    }
    // ---- stage w3 transposed: w3s[ci][k][co] = w3[co][ci][0][k] ----
    for (int idx = tid; idx < W3S_FLOATS; idx += NTHREADS) {
        int co = idx & (Cc - 1);
        int k  = (idx / Cc) % 5;
        int ci = idx / (Cc * 5);
        w3s[idx] = w3[((size_t)co * Cc + ci) * 5 + k];
    }
    for (int idx = tid; idx < W7S_FLOATS; idx += NTHREADS)
        w7s[idx] = w7[idx];
    __syncthreads();

    // thread tile: 4 output channels x 4 width positions
    const int tw  = tid & 31;               // lane -> width group (uniform tc per warp)
    const int tc  = tid >> 5;               // warp -> co group (0..15)
    const int w0  = tw * 4;
    const int co0 = tc * 4;

    // acc2[p][b] holds outputs for channels (co0+2p, co0+2p+1) at width w0+b
    unsigned long long acc2[2][4];
    #pragma unroll
    for (int p = 0; p < 2; p++)
        #pragma unroll
        for (int b = 0; b < 4; b++) acc2[p][b] = 0ull;

    // ---- t3: 1x5 conv with channel mixing (FFMA2 hot loop) ----
    const float* xrow = xs + Cc * WP;       // row h (plane 1)
    for (int ci = 0; ci < Cc; ci++) {
        // x[w0-2 .. w0+5] at padded indices w0 .. w0+7 (16B-aligned)
        const float4* xp4 = reinterpret_cast<const float4*>(xrow + ci * WP + w0);
        float4 x0 = xp4[0];
        float4 x1 = xp4[1];
        float xv[8] = {x0.x, x0.y, x0.z, x0.w, x1.x, x1.y, x1.z, x1.w};
        unsigned long long xd[8];
        #pragma unroll
        for (int j = 0; j < 8; j++) xd[j] = pack2(xv[j], xv[j]);

        const float* wp = w3s + (ci * 5) * Cc + co0;
        #pragma unroll
        for (int k = 0; k < 5; k++) {
            float4 wv = *reinterpret_cast<const float4*>(wp + k * Cc);  // broadcast LDS.128
            unsigned long long wp0 = pack2(wv.x, wv.y);
            unsigned long long wp1 = pack2(wv.z, wv.w);
            #pragma unroll
            for (int b = 0; b < 4; b++) {
                fma2(acc2[0][b], wp0, xd[b + k]);
                fma2(acc2[1][b], wp1, xd[b + k]);
            }
        }
    }

    // unpack t3 accumulators: accf[a][b] = t3(co0+a, w0+b)
    float accf[4][4];
    #pragma unroll
    for (int p = 0; p < 2; p++)
        #pragma unroll
        for (int b = 0; b < 4; b++)
            unpack2(acc2[p][b], accf[2 * p][b], accf[2 * p + 1][b]);

    // ---- epilogue: t1 / t5(roll=1) / max / grouped 1x1 (t7), times t3 ----
    const size_t obase = ((size_t)n * Cc) * Hh * Ww + (size_t)h * Ww;
    #pragma unroll
    for (int a = 0; a < 4; a++) {
        const int c = co0 + a;
        const float* w7c = w7s + c * 9;
        float wk[9];
        #pragma unroll
        for (int q = 0; q < 9; q++) wk[q] = w7c[q];

        const float* rh = xs + (Cc + c) * WP;        // row h, channel c
        #pragma unroll
        for (int b = 0; b < 4; b++) {
            const int w  = w0 + b;
            const int wr = (w == 0) ? (Ww - 1) : (w - 1);   // roll by SHIFT=1

            // t1[c,i,h,w] = x[c,h,w+2i-2] -> padded idx w+2i
            float t1v[3];
            #pragma unroll
            for (int i = 0; i < 3; i++) t1v[i] = rh[w + 2 * i];

            float t7 = 0.f;
            #pragma unroll
            for (int i = 0; i < 3; i++) {            // height offset (row i)
                const float* ri = xs + ((size_t)i * Cc + c) * WP;
                #pragma unroll
                for (int j = 0; j < 3; j++) {        // t5 width offset
                    // t5 = x[c, h+i-1, wr+2j-2] -> plane i, padded idx wr+2j
                    float t5v = ri[wr + 2 * j];
                    float m = fmaxf(t1v[i], t5v);
                    t7 = fmaf(wk[3 * j + i], m, t7);
                }
            }
            out[obase + (size_t)c * Hh * Ww + w] = t7 * accf[a][b];
        }
    }
}

extern "C" void kernel_launch(void* const* d_in, const int* in_sizes, int n_in,
                              void* d_out, int out_size)
{
    const float* x  = (const float*)d_in[0];
    const float* w3 = (const float*)d_in[1];
    const float* w7 = (const float*)d_in[2];
    float* out = (float*)d_out;

    cudaFuncSetAttribute(fused_unfold_conv_kernel,
                         cudaFuncAttributeMaxDynamicSharedMemorySize, SMEM_BYTES);
    fused_unfold_conv_kernel<<<Nn * Hh, NTHREADS, SMEM_BYTES>>>(x, w3, w7, out);
}

// round 3
// speedup vs baseline: 1.6655x; 1.3626x over previous
#include <cuda_runtime.h>

#define Nn 16
#define Cc 64
#define Hh 128
#define Ww 128
#define WP 132   // width padded by 2 on each side

// Two output rows (h0, h0+1) per CTA.
// shared layout (floats):
//   xs [4][Cc][WP]      rows h0-1 .. h0+2, zero-padded     = 33792
//   w3s[Cc][5][Cc]      (ci,k,co) transposed               = 20480
//   w7s[Cc][9]                                             =   576
#define XS_FLOATS   (4 * Cc * WP)
#define W3S_FLOATS  (Cc * 5 * Cc)
#define W7S_FLOATS  (Cc * 9)
#define SMEM_FLOATS (XS_FLOATS + W3S_FLOATS + W7S_FLOATS)
#define SMEM_BYTES  (SMEM_FLOATS * 4)

#define NTHREADS 512

typedef unsigned long long ull;

// ---- packed f32x2 helpers ----
__device__ __forceinline__ ull pack2(float lo, float hi) {
    ull r;
    asm("mov.b64 %0, {%1,%2};" : "=l"(r) : "f"(lo), "f"(hi));
    return r;
}
__device__ __forceinline__ void fma2(ull& d, ull a, ull b) {
    asm("fma.rn.f32x2 %0, %1, %2, %0;" : "+l"(d) : "l"(a), "l"(b));
}
__device__ __forceinline__ void unpack2(ull v, float& lo, float& hi) {
    asm("mov.b64 {%0,%1}, %2;" : "=f"(lo), "=f"(hi) : "l"(v));
}

__global__ __launch_bounds__(NTHREADS, 1)
void fused_unfold_conv_kernel(const float* __restrict__ x,
                              const float* __restrict__ w3,
                              const float* __restrict__ w7,
                              float* __restrict__ out)
{
    extern __shared__ float sh[];
    float* xs  = sh;                        // [4][Cc][WP]
    float* w3s = sh + XS_FLOATS;            // [ci][k][co]
    float* w7s = w3s + W3S_FLOATS;          // [c][9]

    const int tid = threadIdx.x;
    const int h0  = (blockIdx.x & 63) * 2;  // first output row
    const int n   = blockIdx.x >> 6;

    // ---- stage x rows h0-1 .. h0+2 (zero-padded width + height) ----
    const float* xn = x + (size_t)n * Cc * Hh * Ww;
    for (int idx = tid; idx < XS_FLOATS; idx += NTHREADS) {
        int r   = idx / (Cc * WP);          // 0..3 -> row h0-1+r
        int rem = idx - r * (Cc * WP);
        int c   = rem / WP;
        int p   = rem - c * WP;             // padded width index
        int hh  = h0 + r - 1;
        int ww  = p - 2;
        float v = 0.f;
        if ((unsigned)hh < (unsigned)Hh && (unsigned)ww < (unsigned)Ww)
            v = xn[((size_t)c * Hh + hh) * Ww + ww];
        xs[idx] = v;
    }
    // ---- stage w3 transposed: w3s[ci][k][co] = w3[co][ci][0][k] ----
    for (int idx = tid; idx < W3S_FLOATS; idx += NTHREADS) {
        int co = idx & (Cc - 1);
        int k  = (idx / Cc) % 5;
        int ci = idx / (Cc * 5);
        w3s[idx] = w3[((size_t)co * Cc + ci) * 5 + k];
    }
    for (int idx = tid; idx < W7S_FLOATS; idx += NTHREADS)
        w7s[idx] = w7[idx];
    __syncthreads();

    // thread tile: 4 output channels x 4 width positions x 2 rows
    const int tw  = tid & 31;               // lane -> width group
    const int tc  = tid >> 5;               // warp -> co group (0..15)
    const int w0  = tw * 4;
    const int co0 = tc * 4;

    // acc2[p][b][r]: channels (co0+2p, co0+2p+1), width w0+b, row h0+r
    ull acc2[2][4][2];
    #pragma unroll
    for (int p = 0; p < 2; p++)
        #pragma unroll
        for (int b = 0; b < 4; b++) {
            acc2[p][b][0] = 0ull;
            acc2[p][b][1] = 0ull;
        }

    // ---- t3: 1x5 conv with channel mixing (FFMA2 hot loop, 2 rows) ----
    const float* xrow0 = xs + 1 * Cc * WP;  // row h0   (plane 1)
    const float* xrow1 = xs + 2 * Cc * WP;  // row h0+1 (plane 2)
    for (int ci = 0; ci < Cc; ci++) {
        const float4* xp0 = reinterpret_cast<const float4*>(xrow0 + ci * WP + w0);
        const float4* xp1 = reinterpret_cast<const float4*>(xrow1 + ci * WP + w0);
        float4 a0 = xp0[0], a1 = xp0[1];
        float4 b0 = xp1[0], b1 = xp1[1];
        float xv0[8] = {a0.x, a0.y, a0.z, a0.w, a1.x, a1.y, a1.z, a1.w};
        float xv1[8] = {b0.x, b0.y, b0.z, b0.w, b1.x, b1.y, b1.z, b1.w};
        ull xd0[8], xd1[8];
        #pragma unroll
        for (int j = 0; j < 8; j++) {
            xd0[j] = pack2(xv0[j], xv0[j]);
            xd1[j] = pack2(xv1[j], xv1[j]);
        }

        const float* wp = w3s + (ci * 5) * Cc + co0;
        #pragma unroll
        for (int k = 0; k < 5; k++) {
            // direct 8-byte loads of the (co,co+1) pairs — no packing movs
            ull wA = *reinterpret_cast<const ull*>(wp + k * Cc);
            ull wB = *reinterpret_cast<const ull*>(wp + k * Cc + 2);
            #pragma unroll
            for (int b = 0; b < 4; b++) {
                fma2(acc2[0][b][0], wA, xd0[b + k]);
                fma2(acc2[1][b][0], wB, xd0[b + k]);
                fma2(acc2[0][b][1], wA, xd1[b + k]);
                fma2(acc2[1][b][1], wB, xd1[b + k]);
            }
        }
    }

    // ---- epilogue: t1 / t5(roll=1) / max / grouped 1x1 (t7), times t3 ----
    #pragma unroll
    for (int r = 0; r < 2; r++) {
        const int h = h0 + r;
        const size_t obase = ((size_t)n * Cc) * Hh * Ww + (size_t)h * Ww;

        // unpack this row's t3 accumulators
        float accf[4][4];
        #pragma unroll
        for (int p = 0; p < 2; p++)
            #pragma unroll
            for (int b = 0; b < 4; b++)
                unpack2(acc2[p][b][r], accf[2 * p][b], accf[2 * p + 1][b]);

        #pragma unroll
        for (int a = 0; a < 4; a++) {
            const int c = co0 + a;
            const float* w7c = w7s + c * 9;
            float wk[9];
            #pragma unroll
            for (int q = 0; q < 9; q++) wk[q] = w7c[q];

            // row h is plane r+1 for this output row
            const float* rh = xs + ((size_t)(r + 1) * Cc + c) * WP;
            #pragma unroll
            for (int b = 0; b < 4; b++) {
                const int w  = w0 + b;
                const int wr = (w == 0) ? (Ww - 1) : (w - 1);   // roll by SHIFT=1

                float t1v[3];
                #pragma unroll
                for (int i = 0; i < 3; i++) t1v[i] = rh[w + 2 * i];

                float t7 = 0.f;
                #pragma unroll
                for (int i = 0; i < 3; i++) {        // height offset: plane r+i
                    const float* ri = xs + ((size_t)(r + i) * Cc + c) * WP;
                    #pragma unroll
                    for (int j = 0; j < 3; j++) {    // t5 width offset
                        float t5v = ri[wr + 2 * j];
                        float m = fmaxf(t1v[i], t5v);
                        t7 = fmaf(wk[3 * j + i], m, t7);
                    }
                }
                out[obase + (size_t)c * Hh * Ww + w] = t7 * accf[a][b];
            }
        }
    }
}

extern "C" void kernel_launch(void* const* d_in, const int* in_sizes, int n_in,
                              void* d_out, int out_size)
{
    const float* x  = (const float*)d_in[0];
    const float* w3 = (const float*)d_in[1];
    const float* w7 = (const float*)d_in[2];
    float* out = (float*)d_out;

    cudaFuncSetAttribute(fused_unfold_conv_kernel,
                         cudaFuncAttributeMaxDynamicSharedMemorySize, SMEM_BYTES);
    fused_unfold_conv_kernel<<<Nn * (Hh / 2), NTHREADS, SMEM_BYTES>>>(x, w3, w7, out);
}

// round 5
// speedup vs baseline: 1.7174x; 1.0311x over previous
#include <cuda_runtime.h>
#include <cuda_bf16.h>
#include <cstdint>

#define Nn 16
#define Cc 64
#define Hh 128
#define Ww 128
#define WPAD 132

// ---------------- smem layout (bytes, all regions 1024-aligned) ----------------
#define OFF_XPH    0                        // Xp hi: 136 rows x 128B (rows 0..131 used)
#define XP_BYTES   17408
#define OFF_XPL    (OFF_XPH + XP_BYTES)     // 17408
#define OFF_WH     (OFF_XPL + XP_BYTES)     // 34816 : 5 taps x (64ci x 128B co-row)
#define W_BYTES    40960
#define OFF_WL     (OFF_WH + W_BYTES)       // 75776
#define OFF_XS     (OFF_WL + W_BYTES)       // 116736 : f32 xs[3][64][132]
#define XS_FLOATS  (3 * Cc * WPAD)          // 25344
#define OFF_W7     (OFF_XS + XS_FLOATS * 4) // 218112
#define SMEM_BYTES (OFF_W7 + Cc * 9 * 4)    // 220416

#define NTHR 256

#define SWZ(o) ((uint32_t)(o) ^ ((((uint32_t)(o)) >> 3) & 0x70))

// converted weights: [tap(5)][ci(64)][co(64)] bf16 (ci-major rows for ldmatrix.trans)
__device__ __align__(16) __nv_bfloat16 g_Whi[5 * 64 * 64];
__device__ __align__(16) __nv_bfloat16 g_Wlo[5 * 64 * 64];

// ---------------- helpers ----------------
__device__ __forceinline__ uint32_t smem_u32(const void* p) {
    uint32_t a;
    asm("{ .reg .u64 t; cvta.to.shared.u64 t, %1; cvt.u32.u64 %0, t; }" : "=r"(a) : "l"(p));
    return a;
}
__device__ __forceinline__ void ldx4(uint32_t* r, uint32_t addr) {
    asm volatile("ldmatrix.sync.aligned.m8n8.x4.shared.b16 {%0,%1,%2,%3}, [%4];"
                 : "=r"(r[0]), "=r"(r[1]), "=r"(r[2]), "=r"(r[3]) : "r"(addr));
}
__device__ __forceinline__ void ldx2t(uint32_t* r, uint32_t addr) {
    asm volatile("ldmatrix.sync.aligned.m8n8.x2.trans.shared.b16 {%0,%1}, [%2];"
                 : "=r"(r[0]), "=r"(r[1]) : "r"(addr));
}
__device__ __forceinline__ void mma_bf16(float* d, const uint32_t* a, const uint32_t* b) {
    asm volatile(
        "mma.sync.aligned.m16n8k16.row.col.f32.bf16.bf16.f32 "
        "{%0,%1,%2,%3}, {%4,%5,%6,%7}, {%8,%9}, {%0,%1,%2,%3};"
        : "+f"(d[0]), "+f"(d[1]), "+f"(d[2]), "+f"(d[3])
        : "r"(a[0]), "r"(a[1]), "r"(a[2]), "r"(a[3]), "r"(b[0]), "r"(b[1]));
}

// ---------------- pre-kernel: convert w3 to bf16 hi/lo, [tap][ci][co] ----------------
__global__ void convert_w_kernel(const float* __restrict__ w3) {
    int idx = blockIdx.x * 256 + threadIdx.x;
    if (idx >= 5 * 64 * 64) return;
    int t  = idx >> 12;          // tap
    int ci = (idx >> 6) & 63;
    int co = idx & 63;
    float v = w3[((size_t)co * Cc + ci) * 5 + t];
    __nv_bfloat16 hi = __float2bfloat16(v);
    float rem = v - __bfloat162float(hi);
    g_Whi[idx] = hi;
    g_Wlo[idx] = __float2bfloat16(rem);
}

// ---------------- main kernel ----------------
__global__ __launch_bounds__(NTHR, 1)
void fused_mma_kernel(const float* __restrict__ x,
                      const float* __restrict__ w7,
                      float* __restrict__ out)
{
    extern __shared__ char smem[];
    const uint32_t sbase = smem_u32(smem);
    float* xsf = (float*)(smem + OFF_XS);
    float* w7s = (float*)(smem + OFF_W7);

    const int tid  = threadIdx.x;
    const int wid  = tid >> 5;
    const int lane = tid & 31;
    const int h = blockIdx.x & (Hh - 1);
    const int n = blockIdx.x >> 7;

    // ---- stage xs[3][64][132] f32 (rows h-1,h,h+1, zero-padded) ----
    const float* xn = x + (size_t)n * Cc * Hh * Ww;
    for (int idx = tid; idx < XS_FLOATS; idx += NTHR) {
        int r   = idx / (Cc * WPAD);
        int rem = idx - r * (Cc * WPAD);
        int c   = rem / WPAD;
        int p   = rem - c * WPAD;
        int hh  = h + r - 1;
        int ww  = p - 2;
        float v = 0.f;
        if ((unsigned)hh < (unsigned)Hh && (unsigned)ww < (unsigned)Ww)
            v = xn[((size_t)c * Hh + hh) * Ww + ww];
        xsf[idx] = v;
    }
    // ---- stage W (pre-converted bf16 [tap][ci][co]) swizzled, 16B chunks ----
    {
        const uint4* srcH = (const uint4*)g_Whi;
        const uint4* srcL = (const uint4*)g_Wlo;
        for (int g = tid; g < W_BYTES / 16; g += NTHR) {   // 2560 chunks
            int tap = g >> 9;                              // 512 chunks per 8192B tap tile
            uint32_t o   = (uint32_t)(g & 511) * 16;
            uint32_t dst = (uint32_t)tap * 8192 + SWZ(o);
            *(uint4*)(smem + OFF_WH + dst) = srcH[g];
            *(uint4*)(smem + OFF_WL + dst) = srcL[g];
        }
    }
    for (int idx = tid; idx < Cc * 9; idx += NTHR) w7s[idx] = w7[idx];
    __syncthreads();

    // ---- build Xp (transposed, bf16 hi/lo, swizzled): Xp[r][ci] = xs[plane1][ci][r] ----
    for (int t = tid; t < 132 * 32; t += NTHR) {
        int r  = t >> 5;
        int ci = (t & 31) * 2;
        float v0 = xsf[(Cc + ci) * WPAD + r];
        float v1 = xsf[(Cc + ci + 1) * WPAD + r];
        __nv_bfloat16 h0 = __float2bfloat16(v0);
        __nv_bfloat16 h1 = __float2bfloat16(v1);
        __nv_bfloat16 l0 = __float2bfloat16(v0 - __bfloat162float(h0));
        __nv_bfloat16 l1 = __float2bfloat16(v1 - __bfloat162float(h1));
        uint32_t off = SWZ(r * 128 + ci * 2);
        __nv_bfloat162 ph; ph.x = h0; ph.y = h1;
        __nv_bfloat162 pl; pl.x = l0; pl.y = l1;
        *(__nv_bfloat162*)(smem + OFF_XPH + off) = ph;
        *(__nv_bfloat162*)(smem + OFF_XPL + off) = pl;
    }
    __syncthreads();

    // ---- warp tiling: 2 (m) x 4 (n). warp_m in {0,1}: w-rows 64*warp_m..+63;
    //      warp_n in 0..3: co 16*warp_n..+15 ----
    const int warp_m = wid & 1;
    const int warp_n = wid >> 1;
    const int mbase  = 64 * warp_m;

    const int gid = lane >> 2;
    const int tig = lane & 3;
    // ldmatrix lane-address roles
    const int arow   = (lane & 7) + ((lane >> 3) & 1) * 8;  // A: row within 16
    const int acol16 = (lane >> 4) * 16;                    // A: k-half byte offset
    const int brow   = lane & 15;                           // B: ci row within 16

    float acc[4][2][4];
    #pragma unroll
    for (int mt = 0; mt < 4; mt++)
        #pragma unroll
        for (int nt = 0; nt < 2; nt++)
            #pragma unroll
            for (int r = 0; r < 4; r++) acc[mt][nt][r] = 0.f;

    #pragma unroll 1
    for (int tap = 0; tap < 5; tap++) {
        #pragma unroll
        for (int kc = 0; kc < 4; kc++) {
            uint32_t aH[4][4], aL[4][4];
            #pragma unroll
            for (int mt = 0; mt < 4; mt++) {
                uint32_t rel = (uint32_t)((mbase + 16 * mt + tap + arow) * 128
                                          + kc * 32 + acol16);
                uint32_t sw = SWZ(rel);
                ldx4(aH[mt], sbase + OFF_XPH + sw);
                ldx4(aL[mt], sbase + OFF_XPL + sw);
            }
            uint32_t bH[2][2], bL[2][2];
            #pragma unroll
            for (int nt = 0; nt < 2; nt++) {
                uint32_t rel = (uint32_t)((16 * kc + brow) * 128
                                          + 32 * warp_n + 16 * nt);
                uint32_t sw = SWZ(rel) + (uint32_t)tap * 8192;
                ldx2t(bH[nt], sbase + OFF_WH + sw);
                ldx2t(bL[nt], sbase + OFF_WL + sw);
            }
            #pragma unroll
            for (int mt = 0; mt < 4; mt++)
                #pragma unroll
                for (int nt = 0; nt < 2; nt++) {
                    mma_bf16(acc[mt][nt], aH[mt], bH[nt]);  // hi*hi
                    mma_bf16(acc[mt][nt], aH[mt], bL[nt]);  // hi*lo
                    mma_bf16(acc[mt][nt], aL[mt], bH[nt]);  // lo*hi
                }
        }
    }

    // ---- epilogue: t7 per owned (co, w), multiply by t3 acc, store ----
    #pragma unroll
    for (int nt = 0; nt < 2; nt++) {
        #pragma unroll
        for (int j = 0; j < 2; j++) {
            const int co = 16 * warp_n + 8 * nt + 2 * tig + j;
            const float* w7c = w7s + co * 9;
            float wk[9];
            #pragma unroll
            for (int q = 0; q < 9; q++) wk[q] = w7c[q];

            const float* p1 = xsf + (Cc + co) * WPAD;   // plane 1 (row h), channel co
            const size_t ob = (((size_t)n * Cc + co) * Hh + h) * Ww;

            #pragma unroll
            for (int mt = 0; mt < 4; mt++) {
                #pragma unroll
                for (int p = 0; p < 2; p++) {
                    const int wpos = mbase + 16 * mt + gid + 8 * p;
                    const int wr = (wpos == 0) ? (Ww - 1) : (wpos - 1);  // roll SHIFT=1

                    float t1v[3];
                    #pragma unroll
                    for (int i = 0; i < 3; i++) t1v[i] = p1[wpos + 2 * i];

                    float t7 = 0.f;
                    #pragma unroll
                    for (int i = 0; i < 3; i++) {
                        const float* ri = xsf + (i * Cc + co) * WPAD;
                        #pragma unroll
                        for (int jj = 0; jj < 3; jj++) {
                            float t5v = ri[wr + 2 * jj];
                            float m = fmaxf(t1v[i], t5v);
                            t7 = fmaf(wk[3 * jj + i], m, t7);
                        }
                    }
                    out[ob + wpos] = t7 * acc[mt][nt][2 * p + j];
                }
            }
        }
    }
}

extern "C" void kernel_launch(void* const* d_in, const int* in_sizes, int n_in,
                              void* d_out, int out_size)
{
    const float* x  = (const float*)d_in[0];
    const float* w3 = (const float*)d_in[1];
    const float* w7 = (const float*)d_in[2];
    float* out = (float*)d_out;

    convert_w_kernel<<<80, 256>>>(w3);

    cudaFuncSetAttribute(fused_mma_kernel,
                         cudaFuncAttributeMaxDynamicSharedMemorySize, SMEM_BYTES);
    fused_mma_kernel<<<Nn * Hh, NTHR, SMEM_BYTES>>>(x, w7, out);
}

// round 6
// speedup vs baseline: 2.6320x; 1.5325x over previous
#include <cuda_runtime.h>
#include <cuda_bf16.h>
#include <cstdint>

#define Nn 16
#define Cc 64
#define Hh 128
#define Ww 128
#define WPF 136                              // xsf padded row: floats

// ---------------- smem layout (bytes, all regions 1024-aligned) ----------------
#define OFF_XPH    0                        // Xp hi: 136 rows x 128B (rows 0..131 used)
#define XP_BYTES   17408
#define OFF_XPL    (OFF_XPH + XP_BYTES)     // 17408
#define OFF_WH     (OFF_XPL + XP_BYTES)     // 34816 : 5 taps x (64ci x 128B co-row)
#define W_BYTES    40960
#define OFF_WL     (OFF_WH + W_BYTES)       // 75776
#define OFF_XS     (OFF_WL + W_BYTES)       // 116736 : f32 xs[3][64][136]
#define XS_FLOATS  (3 * Cc * WPF)           // 26112
#define OFF_W7     (OFF_XS + XS_FLOATS * 4) // 221184
#define SMEM_BYTES (OFF_W7 + Cc * 9 * 4)    // 223488

#define NTHR 512

#define SWZ(o) ((uint32_t)(o) ^ ((((uint32_t)(o)) >> 3) & 0x70))

// converted weights: [tap(5)][ci(64)][co(64)] bf16
__device__ __align__(16) __nv_bfloat16 g_Whi[5 * 64 * 64];
__device__ __align__(16) __nv_bfloat16 g_Wlo[5 * 64 * 64];

// ---------------- helpers ----------------
__device__ __forceinline__ uint32_t smem_u32(const void* p) {
    uint32_t a;
    asm("{ .reg .u64 t; cvta.to.shared.u64 t, %1; cvt.u32.u64 %0, t; }" : "=r"(a) : "l"(p));
    return a;
}
__device__ __forceinline__ void ldx4(uint32_t* r, uint32_t addr) {
    asm volatile("ldmatrix.sync.aligned.m8n8.x4.shared.b16 {%0,%1,%2,%3}, [%4];"
                 : "=r"(r[0]), "=r"(r[1]), "=r"(r[2]), "=r"(r[3]) : "r"(addr));
}
__device__ __forceinline__ void ldx2t(uint32_t* r, uint32_t addr) {
    asm volatile("ldmatrix.sync.aligned.m8n8.x2.trans.shared.b16 {%0,%1}, [%2];"
                 : "=r"(r[0]), "=r"(r[1]) : "r"(addr));
}
__device__ __forceinline__ void mma_bf16(float* d, const uint32_t* a, const uint32_t* b) {
    asm volatile(
        "mma.sync.aligned.m16n8k16.row.col.f32.bf16.bf16.f32 "
        "{%0,%1,%2,%3}, {%4,%5,%6,%7}, {%8,%9}, {%0,%1,%2,%3};"
        : "+f"(d[0]), "+f"(d[1]), "+f"(d[2]), "+f"(d[3])
        : "r"(a[0]), "r"(a[1]), "r"(a[2]), "r"(a[3]), "r"(b[0]), "r"(b[1]));
}

// ---------------- pre-kernel: convert w3 to bf16 hi/lo, [tap][ci][co] ----------------
__global__ void convert_w_kernel(const float* __restrict__ w3) {
    int idx = blockIdx.x * 256 + threadIdx.x;
    if (idx >= 5 * 64 * 64) return;
    int t  = idx >> 12;
    int ci = (idx >> 6) & 63;
    int co = idx & 63;
    float v = w3[((size_t)co * Cc + ci) * 5 + t];
    __nv_bfloat16 hi = __float2bfloat16(v);
    float rem = v - __bfloat162float(hi);
    g_Whi[idx] = hi;
    g_Wlo[idx] = __float2bfloat16(rem);
}

// ---------------- main kernel ----------------
__global__ __launch_bounds__(NTHR, 1)
void fused_mma_kernel(const float* __restrict__ x,
                      const float* __restrict__ w7,
                      float* __restrict__ out)
{
    extern __shared__ char smem[];
    const uint32_t sbase = smem_u32(smem);
    float* xsf = (float*)(smem + OFF_XS);    // [3][64][WPF], interior at p=4+w
    float* w7s = (float*)(smem + OFF_W7);

    const int tid  = threadIdx.x;
    const int wid  = tid >> 5;
    const int lane = tid & 31;
    const int h = blockIdx.x & (Hh - 1);
    const int n = blockIdx.x >> 7;

    // ---- stage xs interior: 3 planes x 64 c x 32 float4, div-free ----
    const float* xn = x + (size_t)n * Cc * Hh * Ww;
    for (int i = tid; i < 3 * 64 * 32; i += NTHR) {
        int f = i & 31;              // float4 index -> w = 4f
        int c = (i >> 5) & 63;
        int r = i >> 11;             // plane 0..2
        int hh = h + r - 1;
        float4 v = make_float4(0.f, 0.f, 0.f, 0.f);
        if ((unsigned)hh < (unsigned)Hh)
            v = *(const float4*)(xn + ((size_t)c * Hh + hh) * Ww + f * 4);
        // interior starts at p=4 (16B aligned)
        *(float4*)(xsf + (r * Cc + c) * WPF + 4 + f * 4) = v;
    }
    // ---- halo columns p in {2,3,132,133} = zero ----
    for (int i = tid; i < 3 * 64 * 4; i += NTHR) {
        int q = i & 3;               // 0..3 -> p 2,3,132,133
        int c = (i >> 2) & 63;
        int r = i >> 8;
        int p = (q < 2) ? (2 + q) : (130 + q);
        xsf[(r * Cc + c) * WPF + p] = 0.f;
    }
    // ---- stage W (pre-converted bf16 [tap][ci][co]) swizzled, 16B chunks ----
    {
        const uint4* srcH = (const uint4*)g_Whi;
        const uint4* srcL = (const uint4*)g_Wlo;
        for (int g = tid; g < W_BYTES / 16; g += NTHR) {   // 2560 chunks
            int tap = g >> 9;
            uint32_t o   = (uint32_t)(g & 511) * 16;
            uint32_t dst = (uint32_t)tap * 8192 + SWZ(o);
            *(uint4*)(smem + OFF_WH + dst) = srcH[g];
            *(uint4*)(smem + OFF_WL + dst) = srcL[g];
        }
    }
    for (int idx = tid; idx < Cc * 9; idx += NTHR) w7s[idx] = w7[idx];
    __syncthreads();

    // ---- build Xp (transposed bf16 hi/lo, swizzled): Xp[r][ci] = xsf[1][ci][r+2] ----
    // item = ci2 * 132 + r : consecutive lanes -> consecutive r (conflict-free LDS)
    for (int t = tid; t < 32 * 132; t += NTHR) {
        int ci2 = t / 132;
        int r   = t - ci2 * 132;
        int ci  = ci2 * 2;
        float v0 = xsf[(Cc + ci)     * WPF + r + 2];
        float v1 = xsf[(Cc + ci + 1) * WPF + r + 2];
        __nv_bfloat16 h0 = __float2bfloat16(v0);
        __nv_bfloat16 h1 = __float2bfloat16(v1);
        __nv_bfloat16 l0 = __float2bfloat16(v0 - __bfloat162float(h0));
        __nv_bfloat16 l1 = __float2bfloat16(v1 - __bfloat162float(h1));
        uint32_t off = SWZ(r * 128 + ci * 2);
        __nv_bfloat162 ph; ph.x = h0; ph.y = h1;
        __nv_bfloat162 pl; pl.x = l0; pl.y = l1;
        *(__nv_bfloat162*)(smem + OFF_XPH + off) = ph;
        *(__nv_bfloat162*)(smem + OFF_XPL + off) = pl;
    }
    __syncthreads();

    // ---- warp tiling: 4 (m) x 4 (n). warp_m: 32 w-rows; warp_n: 16 co ----
    const int warp_m = wid & 3;
    const int warp_n = wid >> 2;
    const int mbase  = 32 * warp_m;

    const int gid = lane >> 2;
    const int tig = lane & 3;
    const int arow   = (lane & 7) + ((lane >> 3) & 1) * 8;
    const int acol16 = (lane >> 4) * 16;
    const int brow   = lane & 15;

    float acc[2][2][4];
    #pragma unroll
    for (int mt = 0; mt < 2; mt++)
        #pragma unroll
        for (int nt = 0; nt < 2; nt++)
            #pragma unroll
            for (int r = 0; r < 4; r++) acc[mt][nt][r] = 0.f;

    #pragma unroll 1
    for (int tap = 0; tap < 5; tap++) {
        #pragma unroll
        for (int kc = 0; kc < 4; kc++) {
            uint32_t aH[2][4], aL[2][4];
            #pragma unroll
            for (int mt = 0; mt < 2; mt++) {
                uint32_t rel = (uint32_t)((mbase + 16 * mt + tap + arow) * 128
                                          + kc * 32 + acol16);
                uint32_t sw = SWZ(rel);
                ldx4(aH[mt], sbase + OFF_XPH + sw);
                ldx4(aL[mt], sbase + OFF_XPL + sw);
            }
            uint32_t bH[2][2], bL[2][2];
            #pragma unroll
            for (int nt = 0; nt < 2; nt++) {
                uint32_t rel = (uint32_t)((16 * kc + brow) * 128
                                          + 32 * warp_n + 16 * nt);
                uint32_t sw = SWZ(rel) + (uint32_t)tap * 8192;
                ldx2t(bH[nt], sbase + OFF_WH + sw);
                ldx2t(bL[nt], sbase + OFF_WL + sw);
            }
            #pragma unroll
            for (int mt = 0; mt < 2; mt++)
                #pragma unroll
                for (int nt = 0; nt < 2; nt++) {
                    mma_bf16(acc[mt][nt], aH[mt], bH[nt]);  // hi*hi
                    mma_bf16(acc[mt][nt], aH[mt], bL[nt]);  // hi*lo
                    mma_bf16(acc[mt][nt], aL[mt], bH[nt]);  // lo*hi
                }
        }
    }

    // ---- epilogue: t7 per owned (co, w), multiply by t3 acc, store ----
    #pragma unroll
    for (int nt = 0; nt < 2; nt++) {
        #pragma unroll
        for (int j = 0; j < 2; j++) {
            const int co = 16 * warp_n + 8 * nt + 2 * tig + j;
            const float* w7c = w7s + co * 9;
            float wk[9];
            #pragma unroll
            for (int q = 0; q < 9; q++) wk[q] = w7c[q];

            const float* p1 = xsf + (Cc + co) * WPF;    // plane 1, channel co
            const size_t ob = (((size_t)n * Cc + co) * Hh + h) * Ww;

            #pragma unroll
            for (int mt = 0; mt < 2; mt++) {
                #pragma unroll
                for (int p = 0; p < 2; p++) {
                    const int wpos = mbase + 16 * mt + gid + 8 * p;
                    const int wr = (wpos == 0) ? (Ww - 1) : (wpos - 1);

                    float t1v[3];
                    #pragma unroll
                    for (int i = 0; i < 3; i++) t1v[i] = p1[wpos + 2 + 2 * i];

                    float t7 = 0.f;
                    #pragma unroll
                    for (int i = 0; i < 3; i++) {
                        const float* ri = xsf + (i * Cc + co) * WPF;
                        #pragma unroll
                        for (int jj = 0; jj < 3; jj++) {
                            float t5v = ri[wr + 2 + 2 * jj];
                            float m = fmaxf(t1v[i], t5v);
                            t7 = fmaf(wk[3 * jj + i], m, t7);
                        }
                    }
                    out[ob + wpos] = t7 * acc[mt][nt][2 * p + j];
                }
            }
        }
    }
}

extern "C" void kernel_launch(void* const* d_in, const int* in_sizes, int n_in,
                              void* d_out, int out_size)
{
    const float* x  = (const float*)d_in[0];
    const float* w3 = (const float*)d_in[1];
    const float* w7 = (const float*)d_in[2];
    float* out = (float*)d_out;

    convert_w_kernel<<<80, 256>>>(w3);

    cudaFuncSetAttribute(fused_mma_kernel,
                         cudaFuncAttributeMaxDynamicSharedMemorySize, SMEM_BYTES);
    fused_mma_kernel<<<Nn * Hh, NTHR, SMEM_BYTES>>>(x, w7, out);
}

// round 7
// speedup vs baseline: 2.9466x; 1.1195x over previous
#include <cuda_runtime.h>
#include <cuda_bf16.h>
#include <cstdint>

#define Nn 16
#define Cc 64
#define Hh 128
#define Ww 128
#define WPF 140                              // xsf padded row (140 % 32 = 12 -> conflict-free epilogue)

// ---------------- smem layout (bytes, all regions 1024-aligned) ----------------
#define OFF_XPH    0                        // Xp hi: 136 rows x 128B (rows 0..131 used)
#define XP_BYTES   17408
#define OFF_XPL    (OFF_XPH + XP_BYTES)     // 17408
#define OFF_WH     (OFF_XPL + XP_BYTES)     // 34816 : 5 taps x (64ci x 128B co-row)
#define W_BYTES    40960
#define OFF_WL     (OFF_WH + W_BYTES)       // 75776
#define OFF_XS     (OFF_WL + W_BYTES)       // 116736 : f32 xs[3][64][140]
#define XS_FLOATS  (3 * Cc * WPF)           // 26880
#define OFF_W7     (OFF_XS + XS_FLOATS * 4) // 224256
#define SMEM_BYTES (OFF_W7 + Cc * 9 * 4)    // 226560

#define NTHR 512

#define SWZ(o) ((uint32_t)(o) ^ ((((uint32_t)(o)) >> 3) & 0x70))

// converted weights: [tap(5)][ci(64)][co(64)] bf16
__device__ __align__(16) __nv_bfloat16 g_Whi[5 * 64 * 64];
__device__ __align__(16) __nv_bfloat16 g_Wlo[5 * 64 * 64];

// ---------------- helpers ----------------
__device__ __forceinline__ uint32_t smem_u32(const void* p) {
    uint32_t a;
    asm("{ .reg .u64 t; cvta.to.shared.u64 t, %1; cvt.u32.u64 %0, t; }" : "=r"(a) : "l"(p));
    return a;
}
__device__ __forceinline__ void ldx4(uint32_t* r, uint32_t addr) {
    asm volatile("ldmatrix.sync.aligned.m8n8.x4.shared.b16 {%0,%1,%2,%3}, [%4];"
                 : "=r"(r[0]), "=r"(r[1]), "=r"(r[2]), "=r"(r[3]) : "r"(addr));
}
__device__ __forceinline__ void ldx4t(uint32_t* r, uint32_t addr) {
    asm volatile("ldmatrix.sync.aligned.m8n8.x4.trans.shared.b16 {%0,%1,%2,%3}, [%4];"
                 : "=r"(r[0]), "=r"(r[1]), "=r"(r[2]), "=r"(r[3]) : "r"(addr));
}
__device__ __forceinline__ void mma_bf16(float* d, const uint32_t* a, const uint32_t* b) {
    asm volatile(
        "mma.sync.aligned.m16n8k16.row.col.f32.bf16.bf16.f32 "
        "{%0,%1,%2,%3}, {%4,%5,%6,%7}, {%8,%9}, {%0,%1,%2,%3};"
        : "+f"(d[0]), "+f"(d[1]), "+f"(d[2]), "+f"(d[3])
        : "r"(a[0]), "r"(a[1]), "r"(a[2]), "r"(a[3]), "r"(b[0]), "r"(b[1]));
}

// ---------------- pre-kernel: convert w3 to bf16 hi/lo, [tap][ci][co] ----------------
__global__ void convert_w_kernel(const float* __restrict__ w3) {
    int idx = blockIdx.x * 256 + threadIdx.x;
    if (idx >= 5 * 64 * 64) return;
    int t  = idx >> 12;
    int ci = (idx >> 6) & 63;
    int co = idx & 63;
    float v = w3[((size_t)co * Cc + ci) * 5 + t];
    __nv_bfloat16 hi = __float2bfloat16(v);
    float rem = v - __bfloat162float(hi);
    g_Whi[idx] = hi;
    g_Wlo[idx] = __float2bfloat16(rem);
}

// ---------------- main kernel ----------------
__global__ __launch_bounds__(NTHR, 1)
void fused_mma_kernel(const float* __restrict__ x,
                      const float* __restrict__ w7,
                      float* __restrict__ out)
{
    extern __shared__ char smem[];
    const uint32_t sbase = smem_u32(smem);
    float* xsf = (float*)(smem + OFF_XS);    // [3][64][WPF], interior at p=4+w
    float* w7s = (float*)(smem + OFF_W7);

    const int tid  = threadIdx.x;
    const int wid  = tid >> 5;
    const int lane = tid & 31;
    const int h = blockIdx.x & (Hh - 1);
    const int n = blockIdx.x >> 7;

    // ---- stage xs interior: 3 planes x 64 c x 32 float4, div-free ----
    const float* xn = x + (size_t)n * Cc * Hh * Ww;
    for (int i = tid; i < 3 * 64 * 32; i += NTHR) {
        int f = i & 31;
        int c = (i >> 5) & 63;
        int r = i >> 11;
        int hh = h + r - 1;
        float4 v = make_float4(0.f, 0.f, 0.f, 0.f);
        if ((unsigned)hh < (unsigned)Hh)
            v = *(const float4*)(xn + ((size_t)c * Hh + hh) * Ww + f * 4);
        *(float4*)(xsf + (r * Cc + c) * WPF + 4 + f * 4) = v;
    }
    // ---- halo columns p in {2,3,132,133} = zero ----
    for (int i = tid; i < 3 * 64 * 4; i += NTHR) {
        int q = i & 3;
        int c = (i >> 2) & 63;
        int r = i >> 8;
        int p = (q < 2) ? (2 + q) : (130 + q);
        xsf[(r * Cc + c) * WPF + p] = 0.f;
    }
    // ---- stage W (pre-converted bf16 [tap][ci][co]) swizzled, 16B chunks ----
    {
        const uint4* srcH = (const uint4*)g_Whi;
        const uint4* srcL = (const uint4*)g_Wlo;
        for (int g = tid; g < W_BYTES / 16; g += NTHR) {
            int tap = g >> 9;
            uint32_t o   = (uint32_t)(g & 511) * 16;
            uint32_t dst = (uint32_t)tap * 8192 + SWZ(o);
            *(uint4*)(smem + OFF_WH + dst) = srcH[g];
            *(uint4*)(smem + OFF_WL + dst) = srcL[g];
        }
    }
    for (int idx = tid; idx < Cc * 9; idx += NTHR) w7s[idx] = w7[idx];
    __syncthreads();

    // ---- build Xp (transposed bf16 hi/lo, swizzled): Xp[r][ci] = xsf[1][ci][r+2] ----
    for (int t = tid; t < 32 * 132; t += NTHR) {
        int ci2 = t / 132;
        int r   = t - ci2 * 132;
        int ci  = ci2 * 2;
        float v0 = xsf[(Cc + ci)     * WPF + r + 2];
        float v1 = xsf[(Cc + ci + 1) * WPF + r + 2];
        __nv_bfloat16 h0 = __float2bfloat16(v0);
        __nv_bfloat16 h1 = __float2bfloat16(v1);
        __nv_bfloat16 l0 = __float2bfloat16(v0 - __bfloat162float(h0));
        __nv_bfloat16 l1 = __float2bfloat16(v1 - __bfloat162float(h1));
        uint32_t off = SWZ(r * 128 + ci * 2);
        __nv_bfloat162 ph; ph.x = h0; ph.y = h1;
        __nv_bfloat162 pl; pl.x = l0; pl.y = l1;
        *(__nv_bfloat162*)(smem + OFF_XPH + off) = ph;
        *(__nv_bfloat162*)(smem + OFF_XPL + off) = pl;
    }
    __syncthreads();

    // ---- warp tiling: 4 (m) x 4 (n). warp_m: 32 w-rows; warp_n: 16 co ----
    const int warp_m = wid & 3;
    const int warp_n = wid >> 2;
    const int mbase  = 32 * warp_m;

    const int gid = lane >> 2;
    const int tig = lane & 3;
    // A ldmatrix lane roles (x4, non-trans): rows 0..15, halves +16B
    const int arow   = (lane & 7) + ((lane >> 3) & 1) * 8;
    const int acol16 = (lane >> 4) * 16;
    // B ldmatrix lane roles (x4, trans): groups g: row += (g&1)*8, col += ((g>>1)&1)*16
    const int bg  = lane >> 3;
    const int brl = lane & 7;
    const int brow_b = (bg & 1) * 8 + brl;
    const int bcol_b = 32 * warp_n + ((bg >> 1) & 1) * 16;

    float acc[2][2][4];
    #pragma unroll
    for (int mt = 0; mt < 2; mt++)
        #pragma unroll
        for (int nt = 0; nt < 2; nt++)
            #pragma unroll
            for (int r = 0; r < 4; r++) acc[mt][nt][r] = 0.f;

    // double-buffered fragments
    uint32_t aH[2][2][4], aL[2][2][4], bHf[2][4], bLf[2][4];

    // load stage s into buffer buf
    #define LOAD_STAGE(s, buf) do {                                                \
        const int _tap = (s) >> 2, _kc = (s) & 3;                                  \
        _Pragma("unroll")                                                          \
        for (int mt = 0; mt < 2; mt++) {                                           \
            uint32_t rel = (uint32_t)((mbase + 16 * mt + _tap + arow) * 128        \
                                      + _kc * 32 + acol16);                        \
            uint32_t sw = SWZ(rel);                                                \
            ldx4(aH[buf][mt], sbase + OFF_XPH + sw);                               \
            ldx4(aL[buf][mt], sbase + OFF_XPL + sw);                               \
        }                                                                          \
        {                                                                          \
            uint32_t relb = (uint32_t)((16 * _kc + brow_b) * 128 + bcol_b);        \
            uint32_t swb = SWZ(relb) + (uint32_t)_tap * 8192;                      \
            ldx4t(bHf[buf], sbase + OFF_WH + swb);                                 \
            ldx4t(bLf[buf], sbase + OFF_WL + swb);                                 \
        }                                                                          \
    } while (0)

    // 12 MMAs for buffer buf, term-major order (dep distance 4)
    #define MMA_STAGE(buf) do {                                                    \
        _Pragma("unroll")                                                          \
        for (int mt = 0; mt < 2; mt++)                                             \
            _Pragma("unroll")                                                      \
            for (int nt = 0; nt < 2; nt++)                                         \
                mma_bf16(acc[mt][nt], aH[buf][mt], &bHf[buf][2 * nt]);             \
        _Pragma("unroll")                                                          \
        for (int mt = 0; mt < 2; mt++)                                             \
            _Pragma("unroll")                                                      \
            for (int nt = 0; nt < 2; nt++)                                         \
                mma_bf16(acc[mt][nt], aH[buf][mt], &bLf[buf][2 * nt]);             \
        _Pragma("unroll")                                                          \
        for (int mt = 0; mt < 2; mt++)                                             \
            _Pragma("unroll")                                                      \
            for (int nt = 0; nt < 2; nt++)                                         \
                mma_bf16(acc[mt][nt], aL[buf][mt], &bHf[buf][2 * nt]);             \
    } while (0)

    LOAD_STAGE(0, 0);
    #pragma unroll
    for (int s = 0; s < 20; s++) {
        if (s + 1 < 20) {
            if ((s & 1) == 0) LOAD_STAGE(s + 1, 1);
            else              LOAD_STAGE(s + 1, 0);
        }
        if ((s & 1) == 0) MMA_STAGE(0);
        else              MMA_STAGE(1);
    }
    #undef LOAD_STAGE
    #undef MMA_STAGE

    // ---- epilogue: t7 per owned (co, w), multiply by t3 acc, store ----
    #pragma unroll
    for (int nt = 0; nt < 2; nt++) {
        #pragma unroll
        for (int j = 0; j < 2; j++) {
            const int co = 16 * warp_n + 8 * nt + 2 * tig + j;
            const float* w7c = w7s + co * 9;
            float wk[9];
            #pragma unroll
            for (int q = 0; q < 9; q++) wk[q] = w7c[q];

            const float* p1 = xsf + (Cc + co) * WPF;
            const size_t ob = (((size_t)n * Cc + co) * Hh + h) * Ww;

            #pragma unroll
            for (int mt = 0; mt < 2; mt++) {
                #pragma unroll
                for (int p = 0; p < 2; p++) {
                    const int wpos = mbase + 16 * mt + gid + 8 * p;
                    const int wr = (wpos == 0) ? (Ww - 1) : (wpos - 1);

                    float t1v[3];
                    #pragma unroll
                    for (int i = 0; i < 3; i++) t1v[i] = p1[wpos + 2 + 2 * i];

                    float t7 = 0.f;
                    #pragma unroll
                    for (int i = 0; i < 3; i++) {
                        const float* ri = xsf + (i * Cc + co) * WPF;
                        #pragma unroll
                        for (int jj = 0; jj < 3; jj++) {
                            float t5v = ri[wr + 2 + 2 * jj];
                            float m = fmaxf(t1v[i], t5v);
                            t7 = fmaf(wk[3 * jj + i], m, t7);
                        }
                    }
                    out[ob + wpos] = t7 * acc[mt][nt][2 * p + j];
                }
            }
        }
    }
}

extern "C" void kernel_launch(void* const* d_in, const int* in_sizes, int n_in,
                              void* d_out, int out_size)
{
    const float* x  = (const float*)d_in[0];
    const float* w3 = (const float*)d_in[1];
    const float* w7 = (const float*)d_in[2];
    float* out = (float*)d_out;

    convert_w_kernel<<<80, 256>>>(w3);

    cudaFuncSetAttribute(fused_mma_kernel,
                         cudaFuncAttributeMaxDynamicSharedMemorySize, SMEM_BYTES);
    fused_mma_kernel<<<Nn * Hh, NTHR, SMEM_BYTES>>>(x, w7, out);
}

// round 8
// speedup vs baseline: 3.1685x; 1.0753x over previous
#include <cuda_runtime.h>
#include <cuda_bf16.h>
#include <cstdint>

#define Nn 16
#define Cc 64
#define Hh 128
#define Ww 128
#define WPF 140                              // xsf padded row (conflict-free epilogue)

// ---------------- smem layout (bytes) ----------------
#define OFF_XPH    0                        // Xp hi: 136 rows x 128B
#define XP_BYTES   17408
#define OFF_XPL    (OFF_XPH + XP_BYTES)     // 17408
#define OFF_XS     (OFF_XPL + XP_BYTES)     // 34816 : f32 xs[3][64][140]
#define XS_FLOATS  (3 * Cc * WPF)           // 26880
#define OFF_W7     (OFF_XS + XS_FLOATS * 4) // 142336
#define SMEM_BYTES (OFF_W7 + Cc * 9 * 4)    // 144640

#define NTHR 512

#define SWZ(o) ((uint32_t)(o) ^ ((((uint32_t)(o)) >> 3) & 0x70))

// B fragments in mma.sync per-lane order:
// gBfrag[tap(5)][kc(4)][nt8(8)][lane(32)] = {hi_reg0, hi_reg1, lo_reg0, lo_reg1}
__device__ __align__(16) uint4 g_Bfrag[5 * 4 * 8 * 32];

// ---------------- helpers ----------------
__device__ __forceinline__ uint32_t smem_u32(const void* p) {
    uint32_t a;
    asm("{ .reg .u64 t; cvta.to.shared.u64 t, %1; cvt.u32.u64 %0, t; }" : "=r"(a) : "l"(p));
    return a;
}
__device__ __forceinline__ void ldx4(uint32_t* r, uint32_t addr) {
    asm volatile("ldmatrix.sync.aligned.m8n8.x4.shared.b16 {%0,%1,%2,%3}, [%4];"
                 : "=r"(r[0]), "=r"(r[1]), "=r"(r[2]), "=r"(r[3]) : "r"(addr));
}
__device__ __forceinline__ void mma_bf16(float* d, const uint32_t* a, uint32_t b0, uint32_t b1) {
    asm volatile(
        "mma.sync.aligned.m16n8k16.row.col.f32.bf16.bf16.f32 "
        "{%0,%1,%2,%3}, {%4,%5,%6,%7}, {%8,%9}, {%0,%1,%2,%3};"
        : "+f"(d[0]), "+f"(d[1]), "+f"(d[2]), "+f"(d[3])
        : "r"(a[0]), "r"(a[1]), "r"(a[2]), "r"(a[3]), "r"(b0), "r"(b1));
}
__device__ __forceinline__ uint32_t pack_bf16x2(float lo, float hi_) {
    __nv_bfloat162 p;
    p.x = __float2bfloat16(lo);
    p.y = __float2bfloat16(hi_);
    uint32_t r;
    asm("mov.b32 %0, %1;" : "=r"(r) : "r"(*(uint32_t*)&p));
    return r;
}

// ---------------- pre-kernel: build B fragment table ----------------
__global__ void convert_w_kernel(const float* __restrict__ w3) {
    int idx = blockIdx.x * 256 + threadIdx.x;
    if (idx >= 5 * 4 * 8 * 32) return;
    int lane = idx & 31;
    int nt8  = (idx >> 5) & 7;
    int kc   = (idx >> 8) & 3;
    int tap  = idx >> 10;

    int co  = nt8 * 8 + (lane >> 2);
    int ci0 = kc * 16 + (lane & 3) * 2;

    float v[4];
    #pragma unroll
    for (int q = 0; q < 4; q++) {
        int ci = ci0 + (q & 1) + (q >> 1) * 8;   // ci0, ci0+1, ci0+8, ci0+9
        v[q] = w3[((size_t)co * Cc + ci) * 5 + tap];
    }
    float hi[4], lo[4];
    #pragma unroll
    for (int q = 0; q < 4; q++) {
        __nv_bfloat16 hb = __float2bfloat16(v[q]);
        hi[q] = __bfloat162float(hb);
        lo[q] = v[q] - hi[q];
    }
    uint4 frag;
    frag.x = pack_bf16x2(hi[0], hi[1]);   // hi reg0: {B[k],B[k+1]}
    frag.y = pack_bf16x2(hi[2], hi[3]);   // hi reg1: {B[k+8],B[k+9]}
    frag.z = pack_bf16x2(lo[0], lo[1]);   // lo reg0
    frag.w = pack_bf16x2(lo[2], lo[3]);   // lo reg1
    g_Bfrag[idx] = frag;
}

// ---------------- main kernel ----------------
__global__ __launch_bounds__(NTHR, 1)
void fused_mma_kernel(const float* __restrict__ x,
                      const float* __restrict__ w7,
                      float* __restrict__ out)
{
    extern __shared__ char smem[];
    const uint32_t sbase = smem_u32(smem);
    float* xsf = (float*)(smem + OFF_XS);    // [3][64][WPF], interior at p=4+w
    float* w7s = (float*)(smem + OFF_W7);

    const int tid  = threadIdx.x;
    const int wid  = tid >> 5;
    const int lane = tid & 31;
    const int h = blockIdx.x & (Hh - 1);
    const int n = blockIdx.x >> 7;

    // ---- stage xs interior: 3 planes x 64 c x 32 float4, div-free ----
    const float* xn = x + (size_t)n * Cc * Hh * Ww;
    for (int i = tid; i < 3 * 64 * 32; i += NTHR) {
        int f = i & 31;
        int c = (i >> 5) & 63;
        int r = i >> 11;
        int hh = h + r - 1;
        float4 v = make_float4(0.f, 0.f, 0.f, 0.f);
        if ((unsigned)hh < (unsigned)Hh)
            v = *(const float4*)(xn + ((size_t)c * Hh + hh) * Ww + f * 4);
        *(float4*)(xsf + (r * Cc + c) * WPF + 4 + f * 4) = v;
    }
    // ---- halo columns p in {2,3,132,133} = zero ----
    for (int i = tid; i < 3 * 64 * 4; i += NTHR) {
        int q = i & 3;
        int c = (i >> 2) & 63;
        int r = i >> 8;
        int p = (q < 2) ? (2 + q) : (130 + q);
        xsf[(r * Cc + c) * WPF + p] = 0.f;
    }
    for (int idx = tid; idx < Cc * 9; idx += NTHR) w7s[idx] = w7[idx];
    __syncthreads();

    // ---- build Xp (transposed bf16 hi/lo, swizzled): Xp[r][ci] = xsf[1][ci][r+2] ----
    for (int t = tid; t < 32 * 132; t += NTHR) {
        int ci2 = t / 132;
        int r   = t - ci2 * 132;
        int ci  = ci2 * 2;
        float v0 = xsf[(Cc + ci)     * WPF + r + 2];
        float v1 = xsf[(Cc + ci + 1) * WPF + r + 2];
        __nv_bfloat16 h0 = __float2bfloat16(v0);
        __nv_bfloat16 h1 = __float2bfloat16(v1);
        __nv_bfloat16 l0 = __float2bfloat16(v0 - __bfloat162float(h0));
        __nv_bfloat16 l1 = __float2bfloat16(v1 - __bfloat162float(h1));
        uint32_t off = SWZ(r * 128 + ci * 2);
        __nv_bfloat162 ph; ph.x = h0; ph.y = h1;
        __nv_bfloat162 pl; pl.x = l0; pl.y = l1;
        *(__nv_bfloat162*)(smem + OFF_XPH + off) = ph;
        *(__nv_bfloat162*)(smem + OFF_XPL + off) = pl;
    }
    __syncthreads();

    // ---- warp tiling: 4 (m) x 4 (n). warp_m: 32 w-rows; warp_n: 16 co ----
    const int warp_m = wid & 3;
    const int warp_n = wid >> 2;
    const int mbase  = 32 * warp_m;

    const int gid = lane >> 2;
    const int tig = lane & 3;
    const int arow   = (lane & 7) + ((lane >> 3) & 1) * 8;
    const int acol16 = (lane >> 4) * 16;

    // B fragment table slice for this warp: [tap][kc][warp_n*2 + nt][lane]
    const uint4* bt = g_Bfrag + (size_t)(warp_n * 2) * 32 + lane;

    float acc[2][2][4];
    #pragma unroll
    for (int mt = 0; mt < 2; mt++)
        #pragma unroll
        for (int nt = 0; nt < 2; nt++)
            #pragma unroll
            for (int r = 0; r < 4; r++) acc[mt][nt][r] = 0.f;

    // double-buffered fragments
    uint32_t aH[2][2][4], aL[2][2][4];
    uint4 bf[2][2];

    #define LOAD_STAGE(s, buf) do {                                                \
        const int _tap = (s) >> 2, _kc = (s) & 3;                                  \
        _Pragma("unroll")                                                          \
        for (int mt = 0; mt < 2; mt++) {                                           \
            uint32_t rel = (uint32_t)((mbase + 16 * mt + _tap + arow) * 128        \
                                      + _kc * 32 + acol16);                        \
            uint32_t sw = SWZ(rel);                                                \
            ldx4(aH[buf][mt], sbase + OFF_XPH + sw);                               \
            ldx4(aL[buf][mt], sbase + OFF_XPL + sw);                               \
        }                                                                          \
        bf[buf][0] = __ldg(bt + (size_t)(_tap * 4 + _kc) * 256);                   \
        bf[buf][1] = __ldg(bt + (size_t)(_tap * 4 + _kc) * 256 + 32);              \
    } while (0)

    #define MMA_STAGE(buf) do {                                                    \
        _Pragma("unroll")                                                          \
        for (int mt = 0; mt < 2; mt++)                                             \
            _Pragma("unroll")                                                      \
            for (int nt = 0; nt < 2; nt++)                                         \
                mma_bf16(acc[mt][nt], aH[buf][mt], bf[buf][nt].x, bf[buf][nt].y);  \
        _Pragma("unroll")                                                          \
        for (int mt = 0; mt < 2; mt++)                                             \
            _Pragma("unroll")                                                      \
            for (int nt = 0; nt < 2; nt++)                                         \
                mma_bf16(acc[mt][nt], aH[buf][mt], bf[buf][nt].z, bf[buf][nt].w);  \
        _Pragma("unroll")                                                          \
        for (int mt = 0; mt < 2; mt++)                                             \
            _Pragma("unroll")                                                      \
            for (int nt = 0; nt < 2; nt++)                                         \
                mma_bf16(acc[mt][nt], aL[buf][mt], bf[buf][nt].x, bf[buf][nt].y);  \
    } while (0)

    LOAD_STAGE(0, 0);
    #pragma unroll
    for (int s = 0; s < 20; s++) {
        if (s + 1 < 20) {
            if ((s & 1) == 0) LOAD_STAGE(s + 1, 1);
            else              LOAD_STAGE(s + 1, 0);
        }
        if ((s & 1) == 0) MMA_STAGE(0);
        else              MMA_STAGE(1);
    }
    #undef LOAD_STAGE
    #undef MMA_STAGE

    // ---- epilogue: t7 per owned (co, w), multiply by t3 acc, store ----
    #pragma unroll
    for (int nt = 0; nt < 2; nt++) {
        #pragma unroll
        for (int j = 0; j < 2; j++) {
            const int co = 16 * warp_n + 8 * nt + 2 * tig + j;
            const float* w7c = w7s + co * 9;
            float wk[9];
            #pragma unroll
            for (int q = 0; q < 9; q++) wk[q] = w7c[q];

            const float* p1 = xsf + (Cc + co) * WPF;
            const size_t ob = (((size_t)n * Cc + co) * Hh + h) * Ww;

            #pragma unroll
            for (int mt = 0; mt < 2; mt++) {
                #pragma unroll
                for (int p = 0; p < 2; p++) {
                    const int wpos = mbase + 16 * mt + gid + 8 * p;
                    const int wr = (wpos == 0) ? (Ww - 1) : (wpos - 1);

                    float t1v[3];
                    #pragma unroll
                    for (int i = 0; i < 3; i++) t1v[i] = p1[wpos + 2 + 2 * i];

                    float t7 = 0.f;
                    #pragma unroll
                    for (int i = 0; i < 3; i++) {
                        const float* ri = xsf + (i * Cc + co) * WPF;
                        #pragma unroll
                        for (int jj = 0; jj < 3; jj++) {
                            float t5v = ri[wr + 2 + 2 * jj];
                            float m = fmaxf(t1v[i], t5v);
                            t7 = fmaf(wk[3 * jj + i], m, t7);
                        }
                    }
                    out[ob + wpos] = t7 * acc[mt][nt][2 * p + j];
                }
            }
        }
    }
}

extern "C" void kernel_launch(void* const* d_in, const int* in_sizes, int n_in,
                              void* d_out, int out_size)
{
    const float* x  = (const float*)d_in[0];
    const float* w3 = (const float*)d_in[1];
    const float* w7 = (const float*)d_in[2];
    float* out = (float*)d_out;

    convert_w_kernel<<<20, 256>>>(w3);

    cudaFuncSetAttribute(fused_mma_kernel,
                         cudaFuncAttributeMaxDynamicSharedMemorySize, SMEM_BYTES);
    fused_mma_kernel<<<Nn * Hh, NTHR, SMEM_BYTES>>>(x, w7, out);
}

// round 9
// speedup vs baseline: 3.3654x; 1.0622x over previous
#include <cuda_runtime.h>
#include <cuda_bf16.h>
#include <cstdint>

#define Nn 16
#define Cc 64
#define Hh 128
#define Ww 128
#define WPF 76                              // xsf row stride (76%32=12 -> conflict-free epilogue)
#define MROWS 64                            // w-positions per CTA

// ---------------- smem layout (bytes) ----------------
#define OFF_XPH    0                        // Xp hi: 68 rows x 128B = 8704
#define OFF_XPL    9216                     // 1024-aligned
#define OFF_XS     18432                    // f32 xs[3][64][76] = 58368
#define XS_FLOATS  (3 * Cc * WPF)
#define OFF_W7     (OFF_XS + XS_FLOATS * 4) // 76800
#define SMEM_BYTES (OFF_W7 + Cc * 9 * 4)    // 79104

#define NTHR 512

#define SWZ(o) ((uint32_t)(o) ^ ((((uint32_t)(o)) >> 3) & 0x70))

// B fragments in mma.sync per-lane order:
// gBfrag[tap(5)][kc(4)][nt8(8)][lane(32)] = {hi0, hi1, lo0, lo1}
__device__ __align__(16) uint4 g_Bfrag[5 * 4 * 8 * 32];

// ---------------- helpers ----------------
__device__ __forceinline__ uint32_t smem_u32(const void* p) {
    uint32_t a;
    asm("{ .reg .u64 t; cvta.to.shared.u64 t, %1; cvt.u32.u64 %0, t; }" : "=r"(a) : "l"(p));
    return a;
}
__device__ __forceinline__ void ldx4(uint32_t* r, uint32_t addr) {
    asm volatile("ldmatrix.sync.aligned.m8n8.x4.shared.b16 {%0,%1,%2,%3}, [%4];"
                 : "=r"(r[0]), "=r"(r[1]), "=r"(r[2]), "=r"(r[3]) : "r"(addr));
}
__device__ __forceinline__ void mma_bf16(float* d, const uint32_t* a, uint32_t b0, uint32_t b1) {
    asm volatile(
        "mma.sync.aligned.m16n8k16.row.col.f32.bf16.bf16.f32 "
        "{%0,%1,%2,%3}, {%4,%5,%6,%7}, {%8,%9}, {%0,%1,%2,%3};"
        : "+f"(d[0]), "+f"(d[1]), "+f"(d[2]), "+f"(d[3])
        : "r"(a[0]), "r"(a[1]), "r"(a[2]), "r"(a[3]), "r"(b0), "r"(b1));
}
__device__ __forceinline__ uint32_t pack_bf16x2(float lo, float hi_) {
    __nv_bfloat162 p;
    p.x = __float2bfloat16(lo);
    p.y = __float2bfloat16(hi_);
    return *(uint32_t*)&p;
}

// ---------------- pre-kernel: build B fragment table ----------------
__global__ void convert_w_kernel(const float* __restrict__ w3) {
    int idx = blockIdx.x * 256 + threadIdx.x;
    if (idx >= 5 * 4 * 8 * 32) return;
    int lane = idx & 31;
    int nt8  = (idx >> 5) & 7;
    int kc   = (idx >> 8) & 3;
    int tap  = idx >> 10;

    int co  = nt8 * 8 + (lane >> 2);
    int ci0 = kc * 16 + (lane & 3) * 2;

    float v[4], hi[4], lo[4];
    #pragma unroll
    for (int q = 0; q < 4; q++) {
        int ci = ci0 + (q & 1) + (q >> 1) * 8;
        v[q] = w3[((size_t)co * Cc + ci) * 5 + tap];
        __nv_bfloat16 hb = __float2bfloat16(v[q]);
        hi[q] = __bfloat162float(hb);
        lo[q] = v[q] - hi[q];
    }
    uint4 frag;
    frag.x = pack_bf16x2(hi[0], hi[1]);
    frag.y = pack_bf16x2(hi[2], hi[3]);
    frag.z = pack_bf16x2(lo[0], lo[1]);
    frag.w = pack_bf16x2(lo[2], lo[3]);
    g_Bfrag[idx] = frag;
}

// ---------------- main kernel ----------------
__global__ __launch_bounds__(NTHR, 2)
void fused_mma_kernel(const float* __restrict__ x,
                      const float* __restrict__ w7,
                      float* __restrict__ out)
{
    extern __shared__ char smem[];
    const uint32_t sbase = smem_u32(smem);
    float* xsf = (float*)(smem + OFF_XS);    // [3][64][WPF]: xsf[r][c][p] = x[c, h+r-1, w0-4+p]
    float* w7s = (float*)(smem + OFF_W7);

    const int tid  = threadIdx.x;
    const int wid  = tid >> 5;
    const int lane = tid & 31;
    const int wblk = blockIdx.x & 1;
    const int h    = (blockIdx.x >> 1) & (Hh - 1);
    const int n    = blockIdx.x >> 8;
    const int w0   = wblk * MROWS;

    // ---- stage xsf: 3 planes x 64 c x 18 float4 (p = 0..71 -> w = w0-4..w0+67) ----
    const float* xn = x + (size_t)n * Cc * Hh * Ww;
    for (int i = tid; i < 3 * 64 * 18; i += NTHR) {
        int f = i % 18;              // float4 idx: w = w0 - 4 + 4f
        int c = (i / 18) & 63;
        int r = i / (18 * 64);
        int hh = h + r - 1;
        int ww = w0 - 4 + 4 * f;
        float4 v = make_float4(0.f, 0.f, 0.f, 0.f);
        if ((unsigned)hh < (unsigned)Hh && (unsigned)ww < (unsigned)Ww)  // float4 fully in/out
            v = *(const float4*)(xn + ((size_t)c * Hh + hh) * Ww + ww);
        *(float4*)(xsf + (r * Cc + c) * WPF + 4 * f) = v;
    }
    for (int idx = tid; idx < Cc * 9; idx += NTHR) w7s[idx] = w7[idx];
    __syncthreads();

    // ---- build Xp (68 rows x 64ci bf16 hi/lo, swizzled): Xp[r][ci] = xsf[1][ci][r+2] ----
    for (int t = tid; t < 32 * 68; t += NTHR) {
        int ci2 = t / 68;
        int r   = t - ci2 * 68;
        int ci  = ci2 * 2;
        float v0 = xsf[(Cc + ci)     * WPF + r + 2];
        float v1 = xsf[(Cc + ci + 1) * WPF + r + 2];
        __nv_bfloat16 h0 = __float2bfloat16(v0);
        __nv_bfloat16 h1 = __float2bfloat16(v1);
        __nv_bfloat16 l0 = __float2bfloat16(v0 - __bfloat162float(h0));
        __nv_bfloat16 l1 = __float2bfloat16(v1 - __bfloat162float(h1));
        uint32_t off = SWZ(r * 128 + ci * 2);
        __nv_bfloat162 ph; ph.x = h0; ph.y = h1;
        __nv_bfloat162 pl; pl.x = l0; pl.y = l1;
        *(__nv_bfloat162*)(smem + OFF_XPH + off) = ph;
        *(__nv_bfloat162*)(smem + OFF_XPL + off) = pl;
    }
    __syncthreads();

    // ---- warp tiling: 4 (m16) x 4 (n16) over M=64, N=64 ----
    const int warp_m = wid & 3;
    const int warp_n = wid >> 2;
    const int mbase  = 16 * warp_m;

    const int gid = lane >> 2;
    const int tig = lane & 3;
    const int arow   = (lane & 7) + ((lane >> 3) & 1) * 8;
    const int acol16 = (lane >> 4) * 16;

    const uint4* bt = g_Bfrag + (size_t)(warp_n * 2) * 32 + lane;

    float acc[2][4];
    #pragma unroll
    for (int nt = 0; nt < 2; nt++)
        #pragma unroll
        for (int r = 0; r < 4; r++) acc[nt][r] = 0.f;

    uint32_t aH[2][4], aL[2][4];
    uint4 bf[2][2];

    #define LOAD_STAGE(s, buf) do {                                                \
        const int _tap = (s) >> 2, _kc = (s) & 3;                                  \
        uint32_t rel = (uint32_t)((mbase + _tap + arow) * 128 + _kc * 32 + acol16);\
        uint32_t sw = SWZ(rel);                                                    \
        ldx4(aH[buf], sbase + OFF_XPH + sw);                                       \
        ldx4(aL[buf], sbase + OFF_XPL + sw);                                       \
        bf[buf][0] = __ldg(bt + (size_t)(_tap * 4 + _kc) * 256);                   \
        bf[buf][1] = __ldg(bt + (size_t)(_tap * 4 + _kc) * 256 + 32);              \
    } while (0)

    #define MMA_STAGE(buf) do {                                                    \
        _Pragma("unroll")                                                          \
        for (int nt = 0; nt < 2; nt++)                                             \
            mma_bf16(acc[nt], aH[buf], bf[buf][nt].x, bf[buf][nt].y);              \
        _Pragma("unroll")                                                          \
        for (int nt = 0; nt < 2; nt++)                                             \
            mma_bf16(acc[nt], aH[buf], bf[buf][nt].z, bf[buf][nt].w);              \
        _Pragma("unroll")                                                          \
        for (int nt = 0; nt < 2; nt++)                                             \
            mma_bf16(acc[nt], aL[buf], bf[buf][nt].x, bf[buf][nt].y);              \
    } while (0)

    LOAD_STAGE(0, 0);
    #pragma unroll
    for (int s = 0; s < 20; s++) {
        if (s + 1 < 20) {
            if ((s & 1) == 0) LOAD_STAGE(s + 1, 1);
            else              LOAD_STAGE(s + 1, 0);
        }
        if ((s & 1) == 0) MMA_STAGE(0);
        else              MMA_STAGE(1);
    }
    #undef LOAD_STAGE
    #undef MMA_STAGE

    // ---- epilogue: t7 per owned (co, w), multiply by t3 acc, store ----
    #pragma unroll
    for (int nt = 0; nt < 2; nt++) {
        #pragma unroll
        for (int j = 0; j < 2; j++) {
            const int co = 16 * warp_n + 8 * nt + 2 * tig + j;
            const float* w7c = w7s + co * 9;
            float wk[9];
            #pragma unroll
            for (int q = 0; q < 9; q++) wk[q] = w7c[q];

            const float* p1 = xsf + (Cc + co) * WPF;
            const size_t ob = (((size_t)n * Cc + co) * Hh + h) * Ww;

            #pragma unroll
            for (int p = 0; p < 2; p++) {
                const int wl = mbase + gid + 8 * p;    // local w, 0..63
                const int w  = w0 + wl;

                float t1v[3];
                #pragma unroll
                for (int i = 0; i < 3; i++) t1v[i] = p1[wl + 2 + 2 * i];

                float t7 = 0.f;
                if (w != 0) {
                    // wr = w-1 -> t5 p-index = wl + 1 + 2jj (in range 1..67)
                    #pragma unroll
                    for (int i = 0; i < 3; i++) {
                        const float* ri = xsf + (i * Cc + co) * WPF;
                        #pragma unroll
                        for (int jj = 0; jj < 3; jj++) {
                            float t5v = ri[wl + 1 + 2 * jj];
                            float m = fmaxf(t1v[i], t5v);
                            t7 = fmaf(wk[3 * jj + i], m, t7);
                        }
                    }
                } else {
                    // w == 0: roll wraps -> wr = 127; t5 = x[c, h+i-1, 125+2jj] (129 OOB -> 0)
                    #pragma unroll
                    for (int i = 0; i < 3; i++) {
                        int hh = h + i - 1;
                        const float* gr = xn + ((size_t)co * Hh + hh) * Ww;
                        #pragma unroll
                        for (int jj = 0; jj < 3; jj++) {
                            int ww = 125 + 2 * jj;
                            float t5v = 0.f;
                            if ((unsigned)hh < (unsigned)Hh && ww < Ww)
                                t5v = gr[ww];
                            float m = fmaxf(t1v[i], t5v);
                            t7 = fmaf(wk[3 * jj + i], m, t7);
                        }
                    }
                }
                out[ob + w] = t7 * acc[nt][2 * p + j];
            }
        }
    }
}

extern "C" void kernel_launch(void* const* d_in, const int* in_sizes, int n_in,
                              void* d_out, int out_size)
{
    const float* x  = (const float*)d_in[0];
    const float* w3 = (const float*)d_in[1];
    const float* w7 = (const float*)d_in[2];
    float* out = (float*)d_out;

    convert_w_kernel<<<20, 256>>>(w3);

    cudaFuncSetAttribute(fused_mma_kernel,
                         cudaFuncAttributeMaxDynamicSharedMemorySize, SMEM_BYTES);
    fused_mma_kernel<<<Nn * Hh * 2, NTHR, SMEM_BYTES>>>(x, w7, out);
}

// round 10
// speedup vs baseline: 3.6255x; 1.0773x over previous
#include <cuda_runtime.h>
#include <cuda_bf16.h>
#include <cstdint>

#define Nn 16
#define Cc 64
#define Hh 128
#define Ww 128
#define WPF 76                              // xsf row stride (76%32=12 -> conflict-free epilogue)

// CTA: 2 h-rows x 64 w-positions  (M = 128 = 2 row-blocks of 64)
// ---------------- smem layout (bytes) ----------------
#define OFF_XPH    0                        // Xp hi: 136 rows x 128B (68 per h-row block)
#define XP_BYTES   17408
#define OFF_XPL    17408
#define OFF_XS     34816                    // f32 xs[4][64][76] (planes h0-1 .. h0+2)
#define XS_FLOATS  (4 * Cc * WPF)           // 19456
#define OFF_W7     (OFF_XS + XS_FLOATS * 4) // 112640
#define SMEM_BYTES (OFF_W7 + Cc * 9 * 4)    // 114944  -> 2 CTAs/SM

#define NTHR 256

#define SWZ(o) ((uint32_t)(o) ^ ((((uint32_t)(o)) >> 3) & 0x70))

// B fragments in mma.sync per-lane order:
// gBfrag[tap(5)][kc(4)][nt8(8)][lane(32)] = {hi0, hi1, lo0, lo1}
__device__ __align__(16) uint4 g_Bfrag[5 * 4 * 8 * 32];

// ---------------- helpers ----------------
__device__ __forceinline__ uint32_t smem_u32(const void* p) {
    uint32_t a;
    asm("{ .reg .u64 t; cvta.to.shared.u64 t, %1; cvt.u32.u64 %0, t; }" : "=r"(a) : "l"(p));
    return a;
}
__device__ __forceinline__ void ldx4(uint32_t* r, uint32_t addr) {
    asm volatile("ldmatrix.sync.aligned.m8n8.x4.shared.b16 {%0,%1,%2,%3}, [%4];"
                 : "=r"(r[0]), "=r"(r[1]), "=r"(r[2]), "=r"(r[3]) : "r"(addr));
}
__device__ __forceinline__ void mma_bf16(float* d, const uint32_t* a, uint32_t b0, uint32_t b1) {
    asm volatile(
        "mma.sync.aligned.m16n8k16.row.col.f32.bf16.bf16.f32 "
        "{%0,%1,%2,%3}, {%4,%5,%6,%7}, {%8,%9}, {%0,%1,%2,%3};"
        : "+f"(d[0]), "+f"(d[1]), "+f"(d[2]), "+f"(d[3])
        : "r"(a[0]), "r"(a[1]), "r"(a[2]), "r"(a[3]), "r"(b0), "r"(b1));
}
__device__ __forceinline__ uint32_t pack_bf16x2(float lo, float hi_) {
    __nv_bfloat162 p;
    p.x = __float2bfloat16(lo);
    p.y = __float2bfloat16(hi_);
    return *(uint32_t*)&p;
}

// ---------------- pre-kernel: build B fragment table ----------------
__global__ void convert_w_kernel(const float* __restrict__ w3) {
    int idx = blockIdx.x * 256 + threadIdx.x;
    if (idx >= 5 * 4 * 8 * 32) return;
    int lane = idx & 31;
    int nt8  = (idx >> 5) & 7;
    int kc   = (idx >> 8) & 3;
    int tap  = idx >> 10;

    int co  = nt8 * 8 + (lane >> 2);
    int ci0 = kc * 16 + (lane & 3) * 2;

    float v[4], hi[4], lo[4];
    #pragma unroll
    for (int q = 0; q < 4; q++) {
        int ci = ci0 + (q & 1) + (q >> 1) * 8;
        v[q] = w3[((size_t)co * Cc + ci) * 5 + tap];
        __nv_bfloat16 hb = __float2bfloat16(v[q]);
        hi[q] = __bfloat162float(hb);
        lo[q] = v[q] - hi[q];
    }
    uint4 frag;
    frag.x = pack_bf16x2(hi[0], hi[1]);
    frag.y = pack_bf16x2(hi[2], hi[3]);
    frag.z = pack_bf16x2(lo[0], lo[1]);
    frag.w = pack_bf16x2(lo[2], lo[3]);
    g_Bfrag[idx] = frag;
}

// ---------------- main kernel ----------------
__global__ __launch_bounds__(NTHR, 2)
void fused_mma_kernel(const float* __restrict__ x,
                      const float* __restrict__ w7,
                      float* __restrict__ out)
{
    extern __shared__ char smem[];
    const uint32_t sbase = smem_u32(smem);
    float* xsf = (float*)(smem + OFF_XS);    // [4][64][WPF]: xsf[r][c][p] = x[c, h0-1+r, w0-4+p]
    float* w7s = (float*)(smem + OFF_W7);

    const int tid  = threadIdx.x;
    const int wid  = tid >> 5;
    const int lane = tid & 31;
    const int wblk = blockIdx.x & 1;
    const int h0   = ((blockIdx.x >> 1) & 63) * 2;
    const int n    = blockIdx.x >> 7;
    const int w0   = wblk * 64;

    // ---- stage xsf: 4 planes x 64 c x 18 float4 (p = 0..71 -> w = w0-4..w0+67) ----
    const float* xn = x + (size_t)n * Cc * Hh * Ww;
    for (int i = tid; i < 4 * 64 * 18; i += NTHR) {
        int f = i % 18;
        int c = (i / 18) & 63;
        int r = i / (18 * 64);               // plane 0..3 -> h0-1+r
        int hh = h0 + r - 1;
        int ww = w0 - 4 + 4 * f;
        float4 v = make_float4(0.f, 0.f, 0.f, 0.f);
        if ((unsigned)hh < (unsigned)Hh && (unsigned)ww < (unsigned)Ww)
            v = *(const float4*)(xn + ((size_t)c * Hh + hh) * Ww + ww);
        *(float4*)(xsf + (r * Cc + c) * WPF + 4 * f) = v;
    }
    for (int idx = tid; idx < Cc * 9; idx += NTHR) w7s[idx] = w7[idx];
    __syncthreads();

    // ---- build Xp (136 rows x 64ci bf16 hi/lo, swizzled) ----
    // block b (0/1) rows rb 0..67: Xp[68b+rb][ci] = x[ci, h0+b, w0-2+rb] = xsf[1+b][ci][rb+2]
    for (int t = tid; t < 32 * 136; t += NTHR) {
        int ci2 = t / 136;
        int r   = t - ci2 * 136;
        int b   = (r >= 68);
        int rb  = r - 68 * b;
        int ci  = ci2 * 2;
        float v0 = xsf[((1 + b) * Cc + ci)     * WPF + rb + 2];
        float v1 = xsf[((1 + b) * Cc + ci + 1) * WPF + rb + 2];
        __nv_bfloat16 h0b = __float2bfloat16(v0);
        __nv_bfloat16 h1b = __float2bfloat16(v1);
        __nv_bfloat16 l0b = __float2bfloat16(v0 - __bfloat162float(h0b));
        __nv_bfloat16 l1b = __float2bfloat16(v1 - __bfloat162float(h1b));
        uint32_t off = SWZ(r * 128 + ci * 2);
        __nv_bfloat162 ph; ph.x = h0b; ph.y = h1b;
        __nv_bfloat162 pl; pl.x = l0b; pl.y = l1b;
        *(__nv_bfloat162*)(smem + OFF_XPH + off) = ph;
        *(__nv_bfloat162*)(smem + OFF_XPL + off) = pl;
    }
    __syncthreads();

    // ---- warp tiling: 4 (m32) x 2 (n32). warp_m 0,1 -> h0 block; 2,3 -> h0+1 block ----
    const int warp_m = wid & 3;
    const int warp_n = wid >> 2;
    // Xp row base for this warp's m32 tile
    const int arow_base = (warp_m < 2) ? (32 * warp_m) : (68 + 32 * (warp_m - 2));
    const int mlg_base  = 32 * warp_m;       // logical m (0..127)

    const int gid = lane >> 2;
    const int tig = lane & 3;
    const int arow   = (lane & 7) + ((lane >> 3) & 1) * 8;
    const int acol16 = (lane >> 4) * 16;

    // B table base for this warp: nt8 slots [4*warp_n .. 4*warp_n+3]
    const uint4* bt = g_Bfrag + (size_t)(warp_n * 4) * 32 + lane;

    float acc[2][4][4];                      // [mt][nt8][reg]
    #pragma unroll
    for (int mt = 0; mt < 2; mt++)
        #pragma unroll
        for (int nt = 0; nt < 4; nt++)
            #pragma unroll
            for (int r = 0; r < 4; r++) acc[mt][nt][r] = 0.f;

    uint32_t aH[2][2][4], aL[2][2][4];       // [buf][mt][reg]
    uint4 bf[2][4];                          // [buf][nt8]

    #define LOAD_STAGE(s, buf) do {                                                \
        const int _tap = (s) >> 2, _kc = (s) & 3;                                  \
        _Pragma("unroll")                                                          \
        for (int mt = 0; mt < 2; mt++) {                                           \
            uint32_t rel = (uint32_t)((arow_base + 16 * mt + _tap + arow) * 128    \
                                      + _kc * 32 + acol16);                        \
            uint32_t sw = SWZ(rel);                                                \
            ldx4(aH[buf][mt], sbase + OFF_XPH + sw);                               \
            ldx4(aL[buf][mt], sbase + OFF_XPL + sw);                               \
        }                                                                          \
        _Pragma("unroll")                                                          \
        for (int nt = 0; nt < 4; nt++)                                             \
            bf[buf][nt] = __ldg(bt + (size_t)(_tap * 4 + _kc) * 256 + nt * 32);    \
    } while (0)

    #define MMA_STAGE(buf) do {                                                    \
        _Pragma("unroll")                                                          \
        for (int mt = 0; mt < 2; mt++)                                             \
            _Pragma("unroll")                                                      \
            for (int nt = 0; nt < 4; nt++)                                         \
                mma_bf16(acc[mt][nt], aH[buf][mt], bf[buf][nt].x, bf[buf][nt].y);  \
        _Pragma("unroll")                                                          \
        for (int mt = 0; mt < 2; mt++)                                             \
            _Pragma("unroll")                                                      \
            for (int nt = 0; nt < 4; nt++)                                         \
                mma_bf16(acc[mt][nt], aH[buf][mt], bf[buf][nt].z, bf[buf][nt].w);  \
        _Pragma("unroll")                                                          \
        for (int mt = 0; mt < 2; mt++)                                             \
            _Pragma("unroll")                                                      \
            for (int nt = 0; nt < 4; nt++)                                         \
                mma_bf16(acc[mt][nt], aL[buf][mt], bf[buf][nt].x, bf[buf][nt].y);  \
    } while (0)

    LOAD_STAGE(0, 0);
    #pragma unroll
    for (int s = 0; s < 20; s++) {
        if (s + 1 < 20) {
            if ((s & 1) == 0) LOAD_STAGE(s + 1, 1);
            else              LOAD_STAGE(s + 1, 0);
        }
        if ((s & 1) == 0) MMA_STAGE(0);
        else              MMA_STAGE(1);
    }
    #undef LOAD_STAGE
    #undef MMA_STAGE

    // ---- epilogue: t7 per owned (co, h-row, w), multiply by t3 acc, store ----
    #pragma unroll
    for (int nt = 0; nt < 4; nt++) {
        #pragma unroll
        for (int j = 0; j < 2; j++) {
            const int co = 32 * warp_n + 8 * nt + 2 * tig + j;
            const float* w7c = w7s + co * 9;
            float wk[9];
            #pragma unroll
            for (int q = 0; q < 9; q++) wk[q] = w7c[q];

            #pragma unroll
            for (int mt = 0; mt < 2; mt++) {
                #pragma unroll
                for (int p = 0; p < 2; p++) {
                    const int mlg = mlg_base + 16 * mt + gid + 8 * p;  // 0..127
                    const int rr  = mlg >> 6;                          // h-row block
                    const int wl  = mlg & 63;
                    const int w   = w0 + wl;
                    const int h   = h0 + rr;

                    const float* p1 = xsf + ((1 + rr) * Cc + co) * WPF;
                    float t1v[3];
                    #pragma unroll
                    for (int i = 0; i < 3; i++) t1v[i] = p1[wl + 2 + 2 * i];

                    float t7 = 0.f;
                    if (w != 0) {
                        #pragma unroll
                        for (int i = 0; i < 3; i++) {
                            const float* ri = xsf + ((rr + i) * Cc + co) * WPF;
                            #pragma unroll
                            for (int jj = 0; jj < 3; jj++) {
                                float t5v = ri[wl + 1 + 2 * jj];
                                float m = fmaxf(t1v[i], t5v);
                                t7 = fmaf(wk[3 * jj + i], m, t7);
                            }
                        }
                    } else {
                        // w == 0: roll wraps -> wr = 127; t5 = x[c, h+i-1, 125+2jj] (OOB -> 0)
                        #pragma unroll
                        for (int i = 0; i < 3; i++) {
                            int hh = h + i - 1;
                            const float* gr = xn + ((size_t)co * Hh + hh) * Ww;
                            #pragma unroll
                            for (int jj = 0; jj < 3; jj++) {
                                int ww = 125 + 2 * jj;
                                float t5v = 0.f;
                                if ((unsigned)hh < (unsigned)Hh && ww < Ww)
                                    t5v = gr[ww];
                                float m = fmaxf(t1v[i], t5v);
                                t7 = fmaf(wk[3 * jj + i], m, t7);
                            }
                        }
                    }
                    out[(((size_t)n * Cc + co) * Hh + h) * Ww + w] =
                        t7 * acc[mt][nt][2 * p + j];
                }
            }
        }
    }
}

extern "C" void kernel_launch(void* const* d_in, const int* in_sizes, int n_in,
                              void* d_out, int out_size)
{
    const float* x  = (const float*)d_in[0];
    const float* w3 = (const float*)d_in[1];
    const float* w7 = (const float*)d_in[2];
    float* out = (float*)d_out;

    convert_w_kernel<<<20, 256>>>(w3);

    cudaFuncSetAttribute(fused_mma_kernel,
                         cudaFuncAttributeMaxDynamicSharedMemorySize, SMEM_BYTES);
    fused_mma_kernel<<<Nn * 64 * 2, NTHR, SMEM_BYTES>>>(x, w7, out);
}

// round 11
// speedup vs baseline: 3.9300x; 1.0840x over previous
#include <cuda_runtime.h>
#include <cuda_fp16.h>
#include <cstdint>

#define Nn 16
#define Cc 64
#define Hh 128
#define Ww 128
#define WPF 76                              // xsf row stride (76%32=12 -> conflict-free epilogue)

// CTA: 2 h-rows x 64 w-positions  (M = 128 = 2 row-blocks of 64)
// ---------------- smem layout (bytes) ----------------
#define OFF_XPH    0                        // Xp (fp16): 136 rows x 128B (68 per h-row block)
#define XP_BYTES   17408
#define OFF_XS     18432                    // f32 xs[4][64][76]
#define XS_FLOATS  (4 * Cc * WPF)           // 19456
#define OFF_W7     (OFF_XS + XS_FLOATS * 4) // 96256
#define SMEM_BYTES (OFF_W7 + Cc * 9 * 4)    // 98560  -> 2 CTAs/SM

#define NTHR 256

#define SWZ(o) ((uint32_t)(o) ^ ((((uint32_t)(o)) >> 3) & 0x70))

// B fragments (fp16) in mma.sync per-lane order:
// gBfrag[tap(5)][kc(4)][nt8(8)][lane(32)] = {hi0, hi1, lo0, lo1}
__device__ __align__(16) uint4 g_Bfrag[5 * 4 * 8 * 32];

// ---------------- helpers ----------------
__device__ __forceinline__ uint32_t smem_u32(const void* p) {
    uint32_t a;
    asm("{ .reg .u64 t; cvta.to.shared.u64 t, %1; cvt.u32.u64 %0, t; }" : "=r"(a) : "l"(p));
    return a;
}
__device__ __forceinline__ void ldx4(uint32_t* r, uint32_t addr) {
    asm volatile("ldmatrix.sync.aligned.m8n8.x4.shared.b16 {%0,%1,%2,%3}, [%4];"
                 : "=r"(r[0]), "=r"(r[1]), "=r"(r[2]), "=r"(r[3]) : "r"(addr));
}
__device__ __forceinline__ void mma_f16(float* d, const uint32_t* a, uint32_t b0, uint32_t b1) {
    asm volatile(
        "mma.sync.aligned.m16n8k16.row.col.f32.f16.f16.f32 "
        "{%0,%1,%2,%3}, {%4,%5,%6,%7}, {%8,%9}, {%0,%1,%2,%3};"
        : "+f"(d[0]), "+f"(d[1]), "+f"(d[2]), "+f"(d[3])
        : "r"(a[0]), "r"(a[1]), "r"(a[2]), "r"(a[3]), "r"(b0), "r"(b1));
}
__device__ __forceinline__ uint32_t pack_h2(float lo, float hi_) {
    __half2 p;
    p.x = __float2half(lo);
    p.y = __float2half(hi_);
    return *(uint32_t*)&p;
}

// ---------------- pre-kernel: build B fragment table (fp16 hi/lo) ----------------
__global__ void convert_w_kernel(const float* __restrict__ w3) {
    int idx = blockIdx.x * 256 + threadIdx.x;
    if (idx >= 5 * 4 * 8 * 32) return;
    int lane = idx & 31;
    int nt8  = (idx >> 5) & 7;
    int kc   = (idx >> 8) & 3;
    int tap  = idx >> 10;

    int co  = nt8 * 8 + (lane >> 2);
    int ci0 = kc * 16 + (lane & 3) * 2;

    float v[4], hi[4], lo[4];
    #pragma unroll
    for (int q = 0; q < 4; q++) {
        int ci = ci0 + (q & 1) + (q >> 1) * 8;
        v[q] = w3[((size_t)co * Cc + ci) * 5 + tap];
        __half hb = __float2half(v[q]);
        hi[q] = __half2float(hb);
        lo[q] = v[q] - hi[q];
    }
    uint4 frag;
    frag.x = pack_h2(hi[0], hi[1]);
    frag.y = pack_h2(hi[2], hi[3]);
    frag.z = pack_h2(lo[0], lo[1]);
    frag.w = pack_h2(lo[2], lo[3]);
    g_Bfrag[idx] = frag;
}

// ---------------- main kernel ----------------
__global__ __launch_bounds__(NTHR, 2)
void fused_mma_kernel(const float* __restrict__ x,
                      const float* __restrict__ w7,
                      float* __restrict__ out)
{
    extern __shared__ char smem[];
    const uint32_t sbase = smem_u32(smem);
    float* xsf = (float*)(smem + OFF_XS);    // [4][64][WPF]: xsf[r][c][p] = x[c, h0-1+r, w0-4+p]
    float* w7s = (float*)(smem + OFF_W7);

    const int tid  = threadIdx.x;
    const int wid  = tid >> 5;
    const int lane = tid & 31;
    const int wblk = blockIdx.x & 1;
    const int h0   = ((blockIdx.x >> 1) & 63) * 2;
    const int n    = blockIdx.x >> 7;
    const int w0   = wblk * 64;

    // ---- stage xsf: 4 planes x 64 c x 18 float4 ----
    const float* xn = x + (size_t)n * Cc * Hh * Ww;
    for (int i = tid; i < 4 * 64 * 18; i += NTHR) {
        int f = i % 18;
        int c = (i / 18) & 63;
        int r = i / (18 * 64);
        int hh = h0 + r - 1;
        int ww = w0 - 4 + 4 * f;
        float4 v = make_float4(0.f, 0.f, 0.f, 0.f);
        if ((unsigned)hh < (unsigned)Hh && (unsigned)ww < (unsigned)Ww)
            v = *(const float4*)(xn + ((size_t)c * Hh + hh) * Ww + ww);
        *(float4*)(xsf + (r * Cc + c) * WPF + 4 * f) = v;
    }
    for (int idx = tid; idx < Cc * 9; idx += NTHR) w7s[idx] = w7[idx];
    __syncthreads();

    // ---- build Xp (136 rows x 64ci fp16, swizzled) ----
    // block b (0/1) rows rb 0..67: Xp[68b+rb][ci] = x[ci, h0+b, w0-2+rb] = xsf[1+b][ci][rb+2]
    for (int t = tid; t < 32 * 136; t += NTHR) {
        int ci2 = t / 136;
        int r   = t - ci2 * 136;
        int b   = (r >= 68);
        int rb  = r - 68 * b;
        int ci  = ci2 * 2;
        float v0 = xsf[((1 + b) * Cc + ci)     * WPF + rb + 2];
        float v1 = xsf[((1 + b) * Cc + ci + 1) * WPF + rb + 2];
        uint32_t off = SWZ(r * 128 + ci * 2);
        *(uint32_t*)(smem + OFF_XPH + off) = pack_h2(v0, v1);
    }
    __syncthreads();

    // ---- warp tiling: 4 (m32) x 2 (n32). warp_m 0,1 -> h0 block; 2,3 -> h0+1 block ----
    const int warp_m = wid & 3;
    const int warp_n = wid >> 2;
    const int arow_base = (warp_m < 2) ? (32 * warp_m) : (68 + 32 * (warp_m - 2));
    const int mlg_base  = 32 * warp_m;

    const int gid = lane >> 2;
    const int tig = lane & 3;
    const int arow   = (lane & 7) + ((lane >> 3) & 1) * 8;
    const int acol16 = (lane >> 4) * 16;

    const uint4* bt = g_Bfrag + (size_t)(warp_n * 4) * 32 + lane;

    float acc[2][4][4];                      // [mt][nt8][reg]
    #pragma unroll
    for (int mt = 0; mt < 2; mt++)
        #pragma unroll
        for (int nt = 0; nt < 4; nt++)
            #pragma unroll
            for (int r = 0; r < 4; r++) acc[mt][nt][r] = 0.f;

    uint32_t aH[2][2][4];                    // [buf][mt][reg]
    uint4 bf[2][4];                          // [buf][nt8]

    #define LOAD_STAGE(s, buf) do {                                                \
        const int _tap = (s) >> 2, _kc = (s) & 3;                                  \
        _Pragma("unroll")                                                          \
        for (int mt = 0; mt < 2; mt++) {                                           \
            uint32_t rel = (uint32_t)((arow_base + 16 * mt + _tap + arow) * 128    \
                                      + _kc * 32 + acol16);                        \
            ldx4(aH[buf][mt], sbase + OFF_XPH + SWZ(rel));                         \
        }                                                                          \
        _Pragma("unroll")                                                          \
        for (int nt = 0; nt < 4; nt++)                                             \
            bf[buf][nt] = __ldg(bt + (size_t)(_tap * 4 + _kc) * 256 + nt * 32);    \
    } while (0)

    #define MMA_STAGE(buf) do {                                                    \
        _Pragma("unroll")                                                          \
        for (int mt = 0; mt < 2; mt++)                                             \
            _Pragma("unroll")                                                      \
            for (int nt = 0; nt < 4; nt++)                                         \
                mma_f16(acc[mt][nt], aH[buf][mt], bf[buf][nt].x, bf[buf][nt].y);   \
        _Pragma("unroll")                                                          \
        for (int mt = 0; mt < 2; mt++)                                             \
            _Pragma("unroll")                                                      \
            for (int nt = 0; nt < 4; nt++)                                         \
                mma_f16(acc[mt][nt], aH[buf][mt], bf[buf][nt].z, bf[buf][nt].w);   \
    } while (0)

    LOAD_STAGE(0, 0);
    #pragma unroll
    for (int s = 0; s < 20; s++) {
        if (s + 1 < 20) {
            if ((s & 1) == 0) LOAD_STAGE(s + 1, 1);
            else              LOAD_STAGE(s + 1, 0);
        }
        if ((s & 1) == 0) MMA_STAGE(0);
        else              MMA_STAGE(1);
    }
    #undef LOAD_STAGE
    #undef MMA_STAGE

    // ---- epilogue: t7 per owned (co, h-row, w), multiply by t3 acc, store ----
    #pragma unroll
    for (int nt = 0; nt < 4; nt++) {
        #pragma unroll
        for (int j = 0; j < 2; j++) {
            const int co = 32 * warp_n + 8 * nt + 2 * tig + j;
            const float* w7c = w7s + co * 9;
            float wk[9];
            #pragma unroll
            for (int q = 0; q < 9; q++) wk[q] = w7c[q];

            #pragma unroll
            for (int mt = 0; mt < 2; mt++) {
                #pragma unroll
                for (int p = 0; p < 2; p++) {
                    const int mlg = mlg_base + 16 * mt + gid + 8 * p;
                    const int rr  = mlg >> 6;
                    const int wl  = mlg & 63;
                    const int w   = w0 + wl;
                    const int h   = h0 + rr;

                    const float* p1 = xsf + ((1 + rr) * Cc + co) * WPF;
                    float t1v[3];
                    #pragma unroll
                    for (int i = 0; i < 3; i++) t1v[i] = p1[wl + 2 + 2 * i];

                    float t7 = 0.f;
                    if (w != 0) {
                        #pragma unroll
                        for (int i = 0; i < 3; i++) {
                            const float* ri = xsf + ((rr + i) * Cc + co) * WPF;
                            #pragma unroll
                            for (int jj = 0; jj < 3; jj++) {
                                float t5v = ri[wl + 1 + 2 * jj];
                                float m = fmaxf(t1v[i], t5v);
                                t7 = fmaf(wk[3 * jj + i], m, t7);
                            }
                        }
                    } else {
                        // w == 0: roll wraps -> wr = 127; t5 = x[c, h+i-1, 125+2jj] (OOB -> 0)
                        #pragma unroll
                        for (int i = 0; i < 3; i++) {
                            int hh = h + i - 1;
                            const float* gr = xn + ((size_t)co * Hh + hh) * Ww;
                            #pragma unroll
                            for (int jj = 0; jj < 3; jj++) {
                                int ww = 125 + 2 * jj;
                                float t5v = 0.f;
                                if ((unsigned)hh < (unsigned)Hh && ww < Ww)
                                    t5v = gr[ww];
                                float m = fmaxf(t1v[i], t5v);
                                t7 = fmaf(wk[3 * jj + i], m, t7);
                            }
                        }
                    }
                    out[(((size_t)n * Cc + co) * Hh + h) * Ww + w] =
                        t7 * acc[mt][nt][2 * p + j];
                }
            }
        }
    }
}

extern "C" void kernel_launch(void* const* d_in, const int* in_sizes, int n_in,
                              void* d_out, int out_size)
{
    const float* x  = (const float*)d_in[0];
    const float* w3 = (const float*)d_in[1];
    const float* w7 = (const float*)d_in[2];
    float* out = (float*)d_out;

    convert_w_kernel<<<20, 256>>>(w3);

    cudaFuncSetAttribute(fused_mma_kernel,
                         cudaFuncAttributeMaxDynamicSharedMemorySize, SMEM_BYTES);
    fused_mma_kernel<<<Nn * 64 * 2, NTHR, SMEM_BYTES>>>(x, w7, out);
}

// round 12
// speedup vs baseline: 4.2267x; 1.0755x over previous
#include <cuda_runtime.h>
#include <cuda_fp16.h>
#include <cstdint>

#define Nn 16
#define Cc 64
#define Hh 128
#define Ww 128
#define WPF 76                              // xsf row stride

// CTA: 2 h-rows x 64 w-positions  (M = 128 = 2 row-blocks of 64)
// ---------------- smem layout (bytes) ----------------
#define OFF_XPH    0                        // Xp (fp16): 136 rows x 128B
#define XP_BYTES   17408
#define OFF_XS     18432                    // f32 xs[2][64][76] (planes h0, h0+1)
#define XS_FLOATS  (2 * Cc * WPF)           // 9728
#define SMEM_BYTES (OFF_XS + XS_FLOATS * 4) // 57344

#define NTHR 256

#define SWZ(o) ((uint32_t)(o) ^ ((((uint32_t)(o)) >> 3) & 0x70))

// B fragments (fp16) in mma.sync per-lane order:
// gBfrag[tap(5)][kc(4)][nt8(8)][lane(32)] = {hi0, hi1, lo0, lo1}
__device__ __align__(16) uint4 g_Bfrag[5 * 4 * 8 * 32];

// t3 scratch: [n][co][h][w] f32 (same layout as out)
__device__ float g_t3[(size_t)Nn * Cc * Hh * Ww];

// ---------------- helpers ----------------
__device__ __forceinline__ uint32_t smem_u32(const void* p) {
    uint32_t a;
    asm("{ .reg .u64 t; cvta.to.shared.u64 t, %1; cvt.u32.u64 %0, t; }" : "=r"(a) : "l"(p));
    return a;
}
__device__ __forceinline__ void ldx4(uint32_t* r, uint32_t addr) {
    asm volatile("ldmatrix.sync.aligned.m8n8.x4.shared.b16 {%0,%1,%2,%3}, [%4];"
                 : "=r"(r[0]), "=r"(r[1]), "=r"(r[2]), "=r"(r[3]) : "r"(addr));
}
__device__ __forceinline__ void mma_f16(float* d, const uint32_t* a, uint32_t b0, uint32_t b1) {
    asm volatile(
        "mma.sync.aligned.m16n8k16.row.col.f32.f16.f16.f32 "
        "{%0,%1,%2,%3}, {%4,%5,%6,%7}, {%8,%9}, {%0,%1,%2,%3};"
        : "+f"(d[0]), "+f"(d[1]), "+f"(d[2]), "+f"(d[3])
        : "r"(a[0]), "r"(a[1]), "r"(a[2]), "r"(a[3]), "r"(b0), "r"(b1));
}
__device__ __forceinline__ uint32_t pack_h2(float lo, float hi_) {
    __half2 p;
    p.x = __float2half(lo);
    p.y = __float2half(hi_);
    return *(uint32_t*)&p;
}

// ---------------- pre-kernel: build B fragment table (fp16 hi/lo) ----------------
__global__ void convert_w_kernel(const float* __restrict__ w3) {
    int idx = blockIdx.x * 256 + threadIdx.x;
    if (idx >= 5 * 4 * 8 * 32) return;
    int lane = idx & 31;
    int nt8  = (idx >> 5) & 7;
    int kc   = (idx >> 8) & 3;
    int tap  = idx >> 10;

    int co  = nt8 * 8 + (lane >> 2);
    int ci0 = kc * 16 + (lane & 3) * 2;

    float v[4], hi[4], lo[4];
    #pragma unroll
    for (int q = 0; q < 4; q++) {
        int ci = ci0 + (q & 1) + (q >> 1) * 8;
        v[q] = w3[((size_t)co * Cc + ci) * 5 + tap];
        __half hb = __float2half(v[q]);
        hi[q] = __half2float(hb);
        lo[q] = v[q] - hi[q];
    }
    uint4 frag;
    frag.x = pack_h2(hi[0], hi[1]);
    frag.y = pack_h2(hi[2], hi[3]);
    frag.z = pack_h2(lo[0], lo[1]);
    frag.w = pack_h2(lo[2], lo[3]);
    g_Bfrag[idx] = frag;
}

// ---------------- main kernel: pure GEMM -> g_t3 ----------------
__global__ __launch_bounds__(NTHR, 2)
void gemm_kernel(const float* __restrict__ x)
{
    extern __shared__ char smem[];
    const uint32_t sbase = smem_u32(smem);
    float* xsf = (float*)(smem + OFF_XS);    // [2][64][WPF]: xsf[b][c][p] = x[c, h0+b, w0-4+p]

    const int tid  = threadIdx.x;
    const int wid  = tid >> 5;
    const int lane = tid & 31;
    const int wblk = blockIdx.x & 1;
    const int h0   = ((blockIdx.x >> 1) & 63) * 2;
    const int n    = blockIdx.x >> 7;
    const int w0   = wblk * 64;

    // ---- stage xsf: 2 planes x 64 c x 18 float4 ----
    const float* xn = x + (size_t)n * Cc * Hh * Ww;
    for (int i = tid; i < 2 * 64 * 18; i += NTHR) {
        int f = i % 18;
        int c = (i / 18) & 63;
        int r = i / (18 * 64);               // 0/1 -> row h0+r
        int hh = h0 + r;
        int ww = w0 - 4 + 4 * f;
        float4 v = make_float4(0.f, 0.f, 0.f, 0.f);
        if ((unsigned)ww < (unsigned)Ww)
            v = *(const float4*)(xn + ((size_t)c * Hh + hh) * Ww + ww);
        *(float4*)(xsf + (r * Cc + c) * WPF + 4 * f) = v;
    }
    __syncthreads();

    // ---- build Xp (136 rows x 64ci fp16, swizzled) ----
    // block b (0/1) rows rb 0..67: Xp[68b+rb][ci] = x[ci, h0+b, w0-2+rb] = xsf[b][ci][rb+2]
    for (int t = tid; t < 32 * 136; t += NTHR) {
        int ci2 = t / 136;
        int r   = t - ci2 * 136;
        int b   = (r >= 68);
        int rb  = r - 68 * b;
        int ci  = ci2 * 2;
        float v0 = xsf[(b * Cc + ci)     * WPF + rb + 2];
        float v1 = xsf[(b * Cc + ci + 1) * WPF + rb + 2];
        uint32_t off = SWZ(r * 128 + ci * 2);
        *(uint32_t*)(smem + OFF_XPH + off) = pack_h2(v0, v1);
    }
    __syncthreads();

    // ---- warp tiling: 4 (m32) x 2 (n32) ----
    const int warp_m = wid & 3;
    const int warp_n = wid >> 2;
    const int arow_base = (warp_m < 2) ? (32 * warp_m) : (68 + 32 * (warp_m - 2));
    const int mlg_base  = 32 * warp_m;

    const int gid = lane >> 2;
    const int tig = lane & 3;
    const int arow   = (lane & 7) + ((lane >> 3) & 1) * 8;
    const int acol16 = (lane >> 4) * 16;

    const uint4* bt = g_Bfrag + (size_t)(warp_n * 4) * 32 + lane;

    float acc[2][4][4];                      // [mt][nt8][reg]
    #pragma unroll
    for (int mt = 0; mt < 2; mt++)
        #pragma unroll
        for (int nt = 0; nt < 4; nt++)
            #pragma unroll
            for (int r = 0; r < 4; r++) acc[mt][nt][r] = 0.f;

    uint32_t aH[2][2][4];
    uint4 bf[2][4];

    #define LOAD_STAGE(s, buf) do {                                                \
        const int _tap = (s) >> 2, _kc = (s) & 3;                                  \
        _Pragma("unroll")                                                          \
        for (int mt = 0; mt < 2; mt++) {                                           \
            uint32_t rel = (uint32_t)((arow_base + 16 * mt + _tap + arow) * 128    \
                                      + _kc * 32 + acol16);                        \
            ldx4(aH[buf][mt], sbase + OFF_XPH + SWZ(rel));                         \
        }                                                                          \
        _Pragma("unroll")                                                          \
        for (int nt = 0; nt < 4; nt++)                                             \
            bf[buf][nt] = __ldg(bt + (size_t)(_tap * 4 + _kc) * 256 + nt * 32);    \
    } while (0)

    #define MMA_STAGE(buf) do {                                                    \
        _Pragma("unroll")                                                          \
        for (int mt = 0; mt < 2; mt++)                                             \
            _Pragma("unroll")                                                      \
            for (int nt = 0; nt < 4; nt++)                                         \
                mma_f16(acc[mt][nt], aH[buf][mt], bf[buf][nt].x, bf[buf][nt].y);   \
        _Pragma("unroll")                                                          \
        for (int mt = 0; mt < 2; mt++)                                             \
            _Pragma("unroll")                                                      \
            for (int nt = 0; nt < 4; nt++)                                         \
                mma_f16(acc[mt][nt], aH[buf][mt], bf[buf][nt].z, bf[buf][nt].w);   \
    } while (0)

    LOAD_STAGE(0, 0);
    #pragma unroll
    for (int s = 0; s < 20; s++) {
        if (s + 1 < 20) {
            if ((s & 1) == 0) LOAD_STAGE(s + 1, 1);
            else              LOAD_STAGE(s + 1, 0);
        }
        if ((s & 1) == 0) MMA_STAGE(0);
        else              MMA_STAGE(1);
    }
    #undef LOAD_STAGE
    #undef MMA_STAGE

    // ---- store t3 to scratch (layout = out layout) ----
    #pragma unroll
    for (int nt = 0; nt < 4; nt++) {
        #pragma unroll
        for (int j = 0; j < 2; j++) {
            const int co = 32 * warp_n + 8 * nt + 2 * tig + j;
            #pragma unroll
            for (int mt = 0; mt < 2; mt++) {
                #pragma unroll
                for (int p = 0; p < 2; p++) {
                    const int mlg = mlg_base + 16 * mt + gid + 8 * p;
                    const int rr  = mlg >> 6;
                    const int wl  = mlg & 63;
                    g_t3[(((size_t)n * Cc + co) * Hh + (h0 + rr)) * Ww + (w0 + wl)]
                        = acc[mt][nt][2 * p + j];
                }
            }
        }
    }
}

// ---------------- epilogue kernel: t7 * t3 -> out ----------------
// one warp per (n, co, h) row; lane owns 4 consecutive w (float4)
__global__ __launch_bounds__(256)
void epilogue_kernel(const float* __restrict__ x,
                     const float* __restrict__ w7,
                     float* __restrict__ out)
{
    const int row  = blockIdx.x * 8 + (threadIdx.x >> 5);
    const int lane = threadIdx.x & 31;
    const int h  = row & (Hh - 1);
    const int co = (row >> 7) & (Cc - 1);
    const int n  = row >> 13;
    const int w  = lane * 4;

    const float* xc = x + ((size_t)n * Cc + co) * Hh * Ww;

    // windows: win[i][j] = x[co, h+i-1, w-4+j], j = 0..11 (zero-padded)
    float win[3][12];
    #pragma unroll
    for (int i = 0; i < 3; i++) {
        const int hh = h + i - 1;
        if ((unsigned)hh < (unsigned)Hh) {
            const float* xr = xc + (size_t)hh * Ww;
            #pragma unroll
            for (int q = 0; q < 3; q++) {
                const int ww = w - 4 + 4 * q;
                float4 v = make_float4(0.f, 0.f, 0.f, 0.f);
                if ((unsigned)ww < (unsigned)Ww)
                    v = *(const float4*)(xr + ww);
                win[i][4 * q + 0] = v.x;
                win[i][4 * q + 1] = v.y;
                win[i][4 * q + 2] = v.z;
                win[i][4 * q + 3] = v.w;
            }
        } else {
            #pragma unroll
            for (int j = 0; j < 12; j++) win[i][j] = 0.f;
        }
    }

    const float4 t3v = *(const float4*)(g_t3 + ((size_t)row << 7) + w);
    float wk[9];
    #pragma unroll
    for (int q = 0; q < 9; q++) wk[q] = __ldg(w7 + co * 9 + q);

    float res[4];
    #pragma unroll
    for (int k = 0; k < 4; k++) {
        float t7 = 0.f;
        if (k > 0 || w != 0) {
            // wr = w+k-1 ; t5 = win[i][k + 2jj + 1] ; t1 = win[1][k + 2i + 2]
            #pragma unroll
            for (int i = 0; i < 3; i++) {
                const float t1 = win[1][k + 2 * i + 2];
                #pragma unroll
                for (int jj = 0; jj < 3; jj++) {
                    const float t5 = win[i][k + 2 * jj + 1];
                    t7 = fmaf(wk[3 * jj + i], fmaxf(t1, t5), t7);
                }
            }
        } else {
            // w+k == 0: roll wraps -> wr = 127; t5 = x[co, h+i-1, 125+2jj] (129 -> 0)
            #pragma unroll
            for (int i = 0; i < 3; i++) {
                const int hh = h + i - 1;
                const float t1 = win[1][2 * i + 2];
                #pragma unroll
                for (int jj = 0; jj < 3; jj++) {
                    const int ww = 125 + 2 * jj;
                    float t5 = 0.f;
                    if ((unsigned)hh < (unsigned)Hh && ww < Ww)
                        t5 = xc[(size_t)hh * Ww + ww];
                    t7 = fmaf(wk[3 * jj + i], fmaxf(t1, t5), t7);
                }
            }
        }
        res[k] = t7;
    }
    float4 o;
    o.x = res[0] * t3v.x;
    o.y = res[1] * t3v.y;
    o.z = res[2] * t3v.z;
    o.w = res[3] * t3v.w;
    *(float4*)(out + ((size_t)row << 7) + w) = o;
}

extern "C" void kernel_launch(void* const* d_in, const int* in_sizes, int n_in,
                              void* d_out, int out_size)
{
    const float* x  = (const float*)d_in[0];
    const float* w3 = (const float*)d_in[1];
    const float* w7 = (const float*)d_in[2];
    float* out = (float*)d_out;

    convert_w_kernel<<<20, 256>>>(w3);

    cudaFuncSetAttribute(gemm_kernel,
                         cudaFuncAttributeMaxDynamicSharedMemorySize, SMEM_BYTES);
    gemm_kernel<<<Nn * 64 * 2, NTHR, SMEM_BYTES>>>(x);

    epilogue_kernel<<<Nn * Cc * Hh / 8, 256>>>(x, w7, out);
}

// round 13
// speedup vs baseline: 4.6476x; 1.0996x over previous
#include <cuda_runtime.h>
#include <cuda_fp16.h>
#include <cstdint>

#define Nn 16
#define Cc 64
#define Hh 128
#define Ww 128

// gemm CTA: 2 h-rows x 64 w-positions (M = 128). smem = Xp only:
// 144 rows x 128B (block b at row 72b, rows 68..71 of each block unused)
#define SMEM_BYTES (144 * 128)
#define NTHR 256

#define SWZ(o) ((uint32_t)(o) ^ ((((uint32_t)(o)) >> 3) & 0x70))

// B fragments (fp16) in mma.sync per-lane order:
// gBfrag[tap(5)][kc(4)][nt8(8)][lane(32)] = {hi0, hi1, lo0, lo1}
__device__ __align__(16) uint4 g_Bfrag[5 * 4 * 8 * 32];

// t3 scratch: [n][co][h][w] f32 (same layout as out)
__device__ float g_t3[(size_t)Nn * Cc * Hh * Ww];

// pre-transposed fp16 x: [n][h][wp(136)][ci(64)], wp = w+2 (wp 0,1,130..135 zero),
// pre-swizzled within each 128B row: byte = (ci*2) ^ ((wp&7)<<4)
__device__ __align__(16) __half g_xh[(size_t)Nn * Hh * 136 * 64];

// ---------------- helpers ----------------
__device__ __forceinline__ uint32_t smem_u32(const void* p) {
    uint32_t a;
    asm("{ .reg .u64 t; cvta.to.shared.u64 t, %1; cvt.u32.u64 %0, t; }" : "=r"(a) : "l"(p));
    return a;
}
__device__ __forceinline__ void ldx4(uint32_t* r, uint32_t addr) {
    asm volatile("ldmatrix.sync.aligned.m8n8.x4.shared.b16 {%0,%1,%2,%3}, [%4];"
                 : "=r"(r[0]), "=r"(r[1]), "=r"(r[2]), "=r"(r[3]) : "r"(addr));
}
__device__ __forceinline__ void mma_f16(float* d, const uint32_t* a, uint32_t b0, uint32_t b1) {
    asm volatile(
        "mma.sync.aligned.m16n8k16.row.col.f32.f16.f16.f32 "
        "{%0,%1,%2,%3}, {%4,%5,%6,%7}, {%8,%9}, {%0,%1,%2,%3};"
        : "+f"(d[0]), "+f"(d[1]), "+f"(d[2]), "+f"(d[3])
        : "r"(a[0]), "r"(a[1]), "r"(a[2]), "r"(a[3]), "r"(b0), "r"(b1));
}
__device__ __forceinline__ uint32_t pack_h2(float lo, float hi_) {
    __half2 p;
    p.x = __float2half(lo);
    p.y = __float2half(hi_);
    return *(uint32_t*)&p;
}

// ---------------- pre-kernel 1: B fragment table (fp16 hi/lo) ----------------
__global__ void convert_w_kernel(const float* __restrict__ w3) {
    int idx = blockIdx.x * 256 + threadIdx.x;
    if (idx >= 5 * 4 * 8 * 32) return;
    int lane = idx & 31;
    int nt8  = (idx >> 5) & 7;
    int kc   = (idx >> 8) & 3;
    int tap  = idx >> 10;

    int co  = nt8 * 8 + (lane >> 2);
    int ci0 = kc * 16 + (lane & 3) * 2;

    float v[4], hi[4], lo[4];
    #pragma unroll
    for (int q = 0; q < 4; q++) {
        int ci = ci0 + (q & 1) + (q >> 1) * 8;
        v[q] = w3[((size_t)co * Cc + ci) * 5 + tap];
        __half hb = __float2half(v[q]);
        hi[q] = __half2float(hb);
        lo[q] = v[q] - hi[q];
    }
    uint4 frag;
    frag.x = pack_h2(hi[0], hi[1]);
    frag.y = pack_h2(hi[2], hi[3]);
    frag.z = pack_h2(lo[0], lo[1]);
    frag.w = pack_h2(lo[2], lo[3]);
    g_Bfrag[idx] = frag;
}

// ---------------- pre-kernel 2: transpose+convert x -> g_xh ----------------
// one block per (n, h); tile transpose through smem
__global__ __launch_bounds__(256)
void xcvt_kernel(const float* __restrict__ x)
{
    __shared__ float tile[64][129];
    const int nh  = blockIdx.x;
    const int h   = nh & (Hh - 1);
    const int n   = nh >> 7;
    const int tid = threadIdx.x;

    for (int i = tid; i < 64 * 32; i += 256) {
        int f = i & 31, c = i >> 5;
        float4 v = *(const float4*)(x + (((size_t)n * Cc + c) * Hh + h) * Ww + 4 * f);
        tile[c][4 * f + 0] = v.x;
        tile[c][4 * f + 1] = v.y;
        tile[c][4 * f + 2] = v.z;
        tile[c][4 * f + 3] = v.w;
    }
    __syncthreads();

    uint32_t* gh = (uint32_t*)g_xh;
    const size_t rowbase = (size_t)nh * 136;
    for (int i = tid; i < 136 * 32; i += 256) {
        int ci2 = i & 31, wp = i >> 5;
        int w = wp - 2;
        uint32_t val = 0;
        if ((unsigned)w < (unsigned)Ww)
            val = pack_h2(tile[ci2 * 2][w], tile[ci2 * 2 + 1][w]);
        uint32_t boff = ((uint32_t)(ci2 * 4)) ^ ((uint32_t)(wp & 7) << 4);  // pre-swizzle
        gh[(rowbase + wp) * 32 + (boff >> 2)] = val;
    }
}

// ---------------- main kernel: pure GEMM -> g_t3 ----------------
__global__ __launch_bounds__(NTHR, 2)
void gemm_kernel()
{
    extern __shared__ char smem[];
    const uint32_t sbase = smem_u32(smem);

    const int tid  = threadIdx.x;
    const int wid  = tid >> 5;
    const int lane = tid & 31;
    const int wblk = blockIdx.x & 1;
    const int h0   = ((blockIdx.x >> 1) & 63) * 2;
    const int n    = blockIdx.x >> 7;
    const int w0   = wblk * 64;

    // ---- stage Xp: verbatim copy of pre-swizzled fp16 rows ----
    // block b rows rb 0..67 <- g_xh[n][h0+b][w0+rb][*]; smem row = 72b + rb
    {
        const uint4* src0 = (const uint4*)g_xh + ((size_t)(n * Hh + h0)     * 136 + w0) * 8;
        const uint4* src1 = (const uint4*)g_xh + ((size_t)(n * Hh + h0 + 1) * 136 + w0) * 8;
        uint4* d = (uint4*)smem;
        for (int i = tid; i < 1088; i += NTHR) {       // 2 * 68 rows * 8 uint4
            int b = (i >= 544);
            int j = i - 544 * b;                        // rb*8 + q
            uint4 v = b ? src1[j] : src0[j];
            d[b * 576 + j] = v;                         // 72 rows * 8 = 576
        }
    }
    __syncthreads();

    // ---- warp tiling: 4 (m32) x 2 (n32) ----
    const int warp_m = wid & 3;
    const int warp_n = wid >> 2;
    const int arow_base = (warp_m < 2) ? (32 * warp_m) : (72 + 32 * (warp_m - 2));
    const int mlg_base  = 32 * warp_m;

    const int gid = lane >> 2;
    const int tig = lane & 3;
    const int arow   = (lane & 7) + ((lane >> 3) & 1) * 8;
    const int acol16 = (lane >> 4) * 16;

    const uint4* bt = g_Bfrag + (size_t)(warp_n * 4) * 32 + lane;

    float acc[2][4][4];                      // [mt][nt8][reg]
    #pragma unroll
    for (int mt = 0; mt < 2; mt++)
        #pragma unroll
        for (int nt = 0; nt < 4; nt++)
            #pragma unroll
            for (int r = 0; r < 4; r++) acc[mt][nt][r] = 0.f;

    uint32_t aH[2][2][4];
    uint4 bf[2][4];

    #define LOAD_STAGE(s, buf) do {                                                \
        const int _tap = (s) >> 2, _kc = (s) & 3;                                  \
        _Pragma("unroll")                                                          \
        for (int mt = 0; mt < 2; mt++) {                                           \
            uint32_t rel = (uint32_t)((arow_base + 16 * mt + _tap + arow) * 128    \
                                      + _kc * 32 + acol16);                        \
            ldx4(aH[buf][mt], sbase + SWZ(rel));                                   \
        }                                                                          \
        _Pragma("unroll")                                                          \
        for (int nt = 0; nt < 4; nt++)                                             \
            bf[buf][nt] = __ldg(bt + (size_t)(_tap * 4 + _kc) * 256 + nt * 32);    \
    } while (0)

    #define MMA_STAGE(buf) do {                                                    \
        _Pragma("unroll")                                                          \
        for (int mt = 0; mt < 2; mt++)                                             \
            _Pragma("unroll")                                                      \
            for (int nt = 0; nt < 4; nt++)                                         \
                mma_f16(acc[mt][nt], aH[buf][mt], bf[buf][nt].x, bf[buf][nt].y);   \
        _Pragma("unroll")                                                          \
        for (int mt = 0; mt < 2; mt++)                                             \
            _Pragma("unroll")                                                      \
            for (int nt = 0; nt < 4; nt++)                                         \
                mma_f16(acc[mt][nt], aH[buf][mt], bf[buf][nt].z, bf[buf][nt].w);   \
    } while (0)

    LOAD_STAGE(0, 0);
    #pragma unroll
    for (int s = 0; s < 20; s++) {
        if (s + 1 < 20) {
            if ((s & 1) == 0) LOAD_STAGE(s + 1, 1);
            else              LOAD_STAGE(s + 1, 0);
        }
        if ((s & 1) == 0) MMA_STAGE(0);
        else              MMA_STAGE(1);
    }
    #undef LOAD_STAGE
    #undef MMA_STAGE

    // ---- store t3 to scratch (layout = out layout) ----
    #pragma unroll
    for (int nt = 0; nt < 4; nt++) {
        #pragma unroll
        for (int j = 0; j < 2; j++) {
            const int co = 32 * warp_n + 8 * nt + 2 * tig + j;
            #pragma unroll
            for (int mt = 0; mt < 2; mt++) {
                #pragma unroll
                for (int p = 0; p < 2; p++) {
                    const int mlg = mlg_base + 16 * mt + gid + 8 * p;
                    const int rr  = mlg >> 6;
                    const int wl  = mlg & 63;
                    g_t3[(((size_t)n * Cc + co) * Hh + (h0 + rr)) * Ww + (w0 + wl)]
                        = acc[mt][nt][2 * p + j];
                }
            }
        }
    }
}

// ---------------- epilogue kernel: t7 * t3 -> out ----------------
__global__ __launch_bounds__(256)
void epilogue_kernel(const float* __restrict__ x,
                     const float* __restrict__ w7,
                     float* __restrict__ out)
{
    const int row  = blockIdx.x * 8 + (threadIdx.x >> 5);
    const int lane = threadIdx.x & 31;
    const int h  = row & (Hh - 1);
    const int co = (row >> 7) & (Cc - 1);
    const int n  = row >> 13;
    const int w  = lane * 4;

    const float* xc = x + ((size_t)n * Cc + co) * Hh * Ww;

    float win[3][12];
    #pragma unroll
    for (int i = 0; i < 3; i++) {
        const int hh = h + i - 1;
        if ((unsigned)hh < (unsigned)Hh) {
            const float* xr = xc + (size_t)hh * Ww;
            #pragma unroll
            for (int q = 0; q < 3; q++) {
                const int ww = w - 4 + 4 * q;
                float4 v = make_float4(0.f, 0.f, 0.f, 0.f);
                if ((unsigned)ww < (unsigned)Ww)
                    v = *(const float4*)(xr + ww);
                win[i][4 * q + 0] = v.x;
                win[i][4 * q + 1] = v.y;
                win[i][4 * q + 2] = v.z;
                win[i][4 * q + 3] = v.w;
            }
        } else {
            #pragma unroll
            for (int j = 0; j < 12; j++) win[i][j] = 0.f;
        }
    }

    const float4 t3v = *(const float4*)(g_t3 + ((size_t)row << 7) + w);
    float wk[9];
    #pragma unroll
    for (int q = 0; q < 9; q++) wk[q] = __ldg(w7 + co * 9 + q);

    float res[4];
    #pragma unroll
    for (int k = 0; k < 4; k++) {
        float t7 = 0.f;
        if (k > 0 || w != 0) {
            #pragma unroll
            for (int i = 0; i < 3; i++) {
                const float t1 = win[1][k + 2 * i + 2];
                #pragma unroll
                for (int jj = 0; jj < 3; jj++) {
                    const float t5 = win[i][k + 2 * jj + 1];
                    t7 = fmaf(wk[3 * jj + i], fmaxf(t1, t5), t7);
                }
            }
        } else {
            #pragma unroll
            for (int i = 0; i < 3; i++) {
                const int hh = h + i - 1;
                const float t1 = win[1][2 * i + 2];
                #pragma unroll
                for (int jj = 0; jj < 3; jj++) {
                    const int ww = 125 + 2 * jj;
                    float t5 = 0.f;
                    if ((unsigned)hh < (unsigned)Hh && ww < Ww)
                        t5 = xc[(size_t)hh * Ww + ww];
                    t7 = fmaf(wk[3 * jj + i], fmaxf(t1, t5), t7);
                }
            }
        }
        res[k] = t7;
    }
    float4 o;
    o.x = res[0] * t3v.x;
    o.y = res[1] * t3v.y;
    o.z = res[2] * t3v.z;
    o.w = res[3] * t3v.w;
    *(float4*)(out + ((size_t)row << 7) + w) = o;
}

extern "C" void kernel_launch(void* const* d_in, const int* in_sizes, int n_in,
                              void* d_out, int out_size)
{
    const float* x  = (const float*)d_in[0];
    const float* w3 = (const float*)d_in[1];
    const float* w7 = (const float*)d_in[2];
    float* out = (float*)d_out;

    convert_w_kernel<<<20, 256>>>(w3);
    xcvt_kernel<<<Nn * Hh, 256>>>(x);

    cudaFuncSetAttribute(gemm_kernel,
                         cudaFuncAttributeMaxDynamicSharedMemorySize, SMEM_BYTES);
    gemm_kernel<<<Nn * 64 * 2, NTHR, SMEM_BYTES>>>();

    epilogue_kernel<<<Nn * Cc * Hh / 8, 256>>>(x, w7, out);
}